// round 6
// baseline (speedup 1.0000x reference)
#include <cuda_runtime.h>
#include <math.h>

#define NN 8192
#define DD 256
#define EE 262144
#define KK 8
#define LBLK 128   // loss grid: LBLK x LBLK blocks of 64x64

// ---- scratch layout inside the Z region of d_out (16,777,216 floats) ----
// All scratch is dead before the final Z-writing kernel overwrites the region.
#define S_DEG   0                      // 8192 ints
#define S_OFF   8192                   // 8192 ints
#define S_CUR   16384                  // 8192 ints
#define S_ESRC  24576                  // 262144 ints
#define S_EW    286720                 // 262144 floats
#define S_HCAT  1048576                // 4,194,304 floats
#define S_H1    5242880                // 2,097,152 floats
#define S_ZL    7340032                // 2,097,152 floats
#define S_KLP   9437184                // 512 floats
#define S_GLP   9437696                // 16384 floats

// ================= zero degrees =================
__global__ void zero_deg_kernel(int* deg) {
    deg[blockIdx.x * 256 + threadIdx.x] = 0;
}

// ================= histogram of dst (edge_index is INT32: [2, E]) =================
__global__ void hist_kernel(const int* __restrict__ ei, int* deg) {
    int e = blockIdx.x * 256 + threadIdx.x;
    atomicAdd(&deg[ei[EE + e]], 1);
}

// ================= exclusive scan over 8192 degrees (1 block, 256 threads) ========
__global__ void scan_kernel(const int* __restrict__ deg, int* off, int* cur) {
    __shared__ int s[256];
    int tid = threadIdx.x;
    int base = tid * 32;
    int loc[32];
    int sum = 0;
#pragma unroll
    for (int i = 0; i < 32; i++) { loc[i] = deg[base + i]; sum += loc[i]; }
    s[tid] = sum;
    __syncthreads();
    for (int o = 1; o < 256; o <<= 1) {
        int v = (tid >= o) ? s[tid - o] : 0;
        __syncthreads();
        s[tid] += v;
        __syncthreads();
    }
    int run = s[tid] - sum;
#pragma unroll
    for (int i = 0; i < 32; i++) {
        off[base + i] = run;
        cur[base + i] = run;
        run += loc[i];
    }
}

// ================= fill CSR slots =================
__global__ void fill_kernel(const int* __restrict__ ei, const float* __restrict__ w,
                            int* cur, int* esrc, float* ew) {
    int e = blockIdx.x * 256 + threadIdx.x;
    int src = ei[e];
    int dst = ei[EE + e];
    int slot = atomicAdd(&cur[dst], 1);
    esrc[slot] = src;
    ew[slot]   = w[e];
}

// ============ gather conv + fused combine: hcat = [x, mean_agg] ============
__global__ void gather_kernel(const float* __restrict__ x, float* __restrict__ hcat,
                              const int* __restrict__ deg, const int* __restrict__ off,
                              const int* __restrict__ esrc, const float* __restrict__ ew) {
    __shared__ int   ss[256];
    __shared__ float sw[256];
    int n = blockIdx.x, d = threadIdx.x;
    int beg = off[n];
    int dg  = deg[n];
    float acc = 0.f;
    for (int c = 0; c < dg; c += 256) {
        int m = min(256, dg - c);
        if (d < m) { ss[d] = esrc[beg + c + d]; sw[d] = ew[beg + c + d]; }
        __syncthreads();
#pragma unroll 4
        for (int j = 0; j < m; j++)
            acc = fmaf(x[(size_t)ss[j] * DD + d], sw[j], acc);
        __syncthreads();
    }
    hcat[n * 512 + d]       = x[(size_t)n * DD + d];
    hcat[n * 512 + 256 + d] = acc / fmaxf((float)dg, 1.f);
}

// ====== GEMM: C[M,256] = act(A[M,KD] @ W[KD,256] + b) (+res) ======
template<bool RELU, bool RES, int KD>
__global__ void gemm_kernel(const float* __restrict__ A, const float* __restrict__ W,
                            const float* __restrict__ bias, const float* __restrict__ res,
                            float* __restrict__ C) {
    __shared__ __align__(16) float As[16][68];
    __shared__ __align__(16) float Bs[16][68];
    int tid = threadIdx.x;
    int tx = tid & 15, ty = tid >> 4;
    int rowBase = blockIdx.y * 64, colBase = blockIdx.x * 64;
    float acc[4][4];
#pragma unroll
    for (int i = 0; i < 4; i++)
#pragma unroll
        for (int j = 0; j < 4; j++) acc[i][j] = 0.f;

    int arow = tid >> 2, ac = tid & 3;
    int wk = tid >> 4, wj = (tid & 15) << 2;

    for (int k0 = 0; k0 < KD; k0 += 16) {
        float4 av = *(const float4*)(A + (size_t)(rowBase + arow) * KD + k0 + ac * 4);
        As[ac * 4 + 0][arow] = av.x; As[ac * 4 + 1][arow] = av.y;
        As[ac * 4 + 2][arow] = av.z; As[ac * 4 + 3][arow] = av.w;
        *(float4*)&Bs[wk][wj] = *(const float4*)(W + (size_t)(k0 + wk) * 256 + colBase + wj);
        __syncthreads();
#pragma unroll
        for (int k = 0; k < 16; k++) {
            float4 a = *(float4*)&As[k][ty * 4];
            float4 b = *(float4*)&Bs[k][tx * 4];
            acc[0][0] = fmaf(a.x, b.x, acc[0][0]); acc[0][1] = fmaf(a.x, b.y, acc[0][1]);
            acc[0][2] = fmaf(a.x, b.z, acc[0][2]); acc[0][3] = fmaf(a.x, b.w, acc[0][3]);
            acc[1][0] = fmaf(a.y, b.x, acc[1][0]); acc[1][1] = fmaf(a.y, b.y, acc[1][1]);
            acc[1][2] = fmaf(a.y, b.z, acc[1][2]); acc[1][3] = fmaf(a.y, b.w, acc[1][3]);
            acc[2][0] = fmaf(a.z, b.x, acc[2][0]); acc[2][1] = fmaf(a.z, b.y, acc[2][1]);
            acc[2][2] = fmaf(a.z, b.z, acc[2][2]); acc[2][3] = fmaf(a.z, b.w, acc[2][3]);
            acc[3][0] = fmaf(a.w, b.x, acc[3][0]); acc[3][1] = fmaf(a.w, b.y, acc[3][1]);
            acc[3][2] = fmaf(a.w, b.z, acc[3][2]); acc[3][3] = fmaf(a.w, b.w, acc[3][3]);
        }
        __syncthreads();
    }

    float4 bv = *(const float4*)(bias + colBase + tx * 4);
#pragma unroll
    for (int ii = 0; ii < 4; ii++) {
        int r = rowBase + ty * 4 + ii;
        float4 o;
        o.x = acc[ii][0] + bv.x; o.y = acc[ii][1] + bv.y;
        o.z = acc[ii][2] + bv.z; o.w = acc[ii][3] + bv.w;
        if (RELU) {
            o.x = fmaxf(o.x, 0.f); o.y = fmaxf(o.y, 0.f);
            o.z = fmaxf(o.z, 0.f); o.w = fmaxf(o.w, 0.f);
        }
        if (RES) {
            float4 rv = *(const float4*)(res + (size_t)r * 256 + colBase + (tx << 2));
            o.x += rv.x; o.y += rv.y; o.z += rv.z; o.w += rv.w;
        }
        *(float4*)(C + (size_t)r * 256 + colBase + (tx << 2)) = o;
    }
}

// ====== fused heads: compute mu/lv tiles in-register from enc2@W3 / enc2@W4 ======
// MODE 0: write Zl = mu + sigma*mean_k(eps), KL partials.   (pre-loss)
// MODE 1: write Z[n,k,:] = mu + sigma*eps.                  (final kernel)
template<int MODE>
__global__ void heads_kernel(const float* __restrict__ enc2,
                             const float* __restrict__ W3, const float* __restrict__ b3,
                             const float* __restrict__ W4, const float* __restrict__ b4,
                             const float* __restrict__ eps,
                             float* __restrict__ dst,       // MODE0: Zl   MODE1: Z
                             float* __restrict__ klpart) {
    __shared__ __align__(16) float As[16][68];
    __shared__ __align__(16) float B3s[16][68];
    __shared__ __align__(16) float B4s[16][68];
    int tid = threadIdx.x;
    int tx = tid & 15, ty = tid >> 4;
    int rowBase = blockIdx.y * 64, colBase = blockIdx.x * 64;
    float am[4][4], al[4][4];
#pragma unroll
    for (int i = 0; i < 4; i++)
#pragma unroll
        for (int j = 0; j < 4; j++) { am[i][j] = 0.f; al[i][j] = 0.f; }

    int arow = tid >> 2, ac = tid & 3;
    int wk = tid >> 4, wj = (tid & 15) << 2;

    for (int k0 = 0; k0 < 256; k0 += 16) {
        float4 av = *(const float4*)(enc2 + (size_t)(rowBase + arow) * 256 + k0 + ac * 4);
        As[ac * 4 + 0][arow] = av.x; As[ac * 4 + 1][arow] = av.y;
        As[ac * 4 + 2][arow] = av.z; As[ac * 4 + 3][arow] = av.w;
        *(float4*)&B3s[wk][wj] = *(const float4*)(W3 + (size_t)(k0 + wk) * 256 + colBase + wj);
        *(float4*)&B4s[wk][wj] = *(const float4*)(W4 + (size_t)(k0 + wk) * 256 + colBase + wj);
        __syncthreads();
#pragma unroll
        for (int k = 0; k < 16; k++) {
            float4 a  = *(float4*)&As[k][ty * 4];
            float4 b3v = *(float4*)&B3s[k][tx * 4];
            float4 b4v = *(float4*)&B4s[k][tx * 4];
            float aa[4] = {a.x, a.y, a.z, a.w};
            float m3[4] = {b3v.x, b3v.y, b3v.z, b3v.w};
            float m4[4] = {b4v.x, b4v.y, b4v.z, b4v.w};
#pragma unroll
            for (int ii = 0; ii < 4; ii++)
#pragma unroll
                for (int jj = 0; jj < 4; jj++) {
                    am[ii][jj] = fmaf(aa[ii], m3[jj], am[ii][jj]);
                    al[ii][jj] = fmaf(aa[ii], m4[jj], al[ii][jj]);
                }
        }
        __syncthreads();
    }

    float4 bv3 = *(const float4*)(b3 + colBase + tx * 4);
    float4 bv4 = *(const float4*)(b4 + colBase + tx * 4);
    float bb3[4] = {bv3.x, bv3.y, bv3.z, bv3.w};
    float bb4[4] = {bv4.x, bv4.y, bv4.z, bv4.w};

    float klsum = 0.f;
#pragma unroll
    for (int ii = 0; ii < 4; ii++) {
        int n = rowBase + ty * 4 + ii;
        int col = colBase + (tx << 2);
        float mu[4], lv[4], sg[4];
#pragma unroll
        for (int jj = 0; jj < 4; jj++) {
            mu[jj] = am[ii][jj] + bb3[jj];
            lv[jj] = al[ii][jj] + bb4[jj];
            sg[jj] = expf(0.5f * lv[jj]);
        }
        if (MODE == 0) {
            float4 es = make_float4(0.f, 0.f, 0.f, 0.f);
#pragma unroll
            for (int k = 0; k < KK; k++) {
                float4 e = *(const float4*)(eps + (size_t)(n * KK + k) * DD + col);
                es.x += e.x; es.y += e.y; es.z += e.z; es.w += e.w;
            }
            float4 o;
            o.x = fmaf(sg[0], es.x * 0.125f, mu[0]);
            o.y = fmaf(sg[1], es.y * 0.125f, mu[1]);
            o.z = fmaf(sg[2], es.z * 0.125f, mu[2]);
            o.w = fmaf(sg[3], es.w * 0.125f, mu[3]);
            *(float4*)(dst + (size_t)n * DD + col) = o;
#pragma unroll
            for (int jj = 0; jj < 4; jj++)
                klsum += 1.f + lv[jj] - mu[jj] * mu[jj] - sg[jj] * sg[jj];
        } else {
#pragma unroll
            for (int k = 0; k < KK; k++) {
                float4 e = *(const float4*)(eps + (size_t)(n * KK + k) * DD + col);
                float4 o;
                o.x = fmaf(sg[0], e.x, mu[0]);
                o.y = fmaf(sg[1], e.y, mu[1]);
                o.z = fmaf(sg[2], e.z, mu[2]);
                o.w = fmaf(sg[3], e.w, mu[3]);
                *(float4*)(dst + (size_t)(n * KK + k) * DD + col) = o;
            }
        }
    }

    if (MODE == 0) {
        __shared__ float sred[256];
        sred[tid] = klsum; __syncthreads();
        for (int s = 128; s > 0; s >>= 1) {
            if (tid < s) sred[tid] += sred[tid + s];
            __syncthreads();
        }
        if (tid == 0) klpart[blockIdx.y * 4 + blockIdx.x] = sred[0];
    }
}

// ====== fused Zl@Zl^T + BCE-with-logits, symmetric half, per-block partials ======
__global__ void loss_kernel(const float* __restrict__ Zl, const float* __restrict__ ADJ,
                            float* __restrict__ glpart) {
    int bi = blockIdx.y, bj = blockIdx.x;
    int tid = threadIdx.x;
    if (bj < bi) {
        if (tid == 0) glpart[bi * LBLK + bj] = 0.f;
        return;
    }
    __shared__ __align__(16) float As[16][68];
    __shared__ __align__(16) float Bs[16][68];
    __shared__ float Ts[64][65];
    int tx = tid & 15, ty = tid >> 4;
    int rowBase = bi * 64, colBase = bj * 64;
    float acc[4][4];
#pragma unroll
    for (int i = 0; i < 4; i++)
#pragma unroll
        for (int j = 0; j < 4; j++) acc[i][j] = 0.f;

    int arow = tid >> 2, ac = tid & 3;
    for (int k0 = 0; k0 < 256; k0 += 16) {
        float4 av = *(const float4*)(Zl + (size_t)(rowBase + arow) * 256 + k0 + ac * 4);
        As[ac * 4 + 0][arow] = av.x; As[ac * 4 + 1][arow] = av.y;
        As[ac * 4 + 2][arow] = av.z; As[ac * 4 + 3][arow] = av.w;
        float4 bv = *(const float4*)(Zl + (size_t)(colBase + arow) * 256 + k0 + ac * 4);
        Bs[ac * 4 + 0][arow] = bv.x; Bs[ac * 4 + 1][arow] = bv.y;
        Bs[ac * 4 + 2][arow] = bv.z; Bs[ac * 4 + 3][arow] = bv.w;
        __syncthreads();
#pragma unroll
        for (int k = 0; k < 16; k++) {
            float4 a = *(float4*)&As[k][ty * 4];
            float4 b = *(float4*)&Bs[k][tx * 4];
            acc[0][0] = fmaf(a.x, b.x, acc[0][0]); acc[0][1] = fmaf(a.x, b.y, acc[0][1]);
            acc[0][2] = fmaf(a.x, b.z, acc[0][2]); acc[0][3] = fmaf(a.x, b.w, acc[0][3]);
            acc[1][0] = fmaf(a.y, b.x, acc[1][0]); acc[1][1] = fmaf(a.y, b.y, acc[1][1]);
            acc[1][2] = fmaf(a.y, b.z, acc[1][2]); acc[1][3] = fmaf(a.y, b.w, acc[1][3]);
            acc[2][0] = fmaf(a.z, b.x, acc[2][0]); acc[2][1] = fmaf(a.z, b.y, acc[2][1]);
            acc[2][2] = fmaf(a.z, b.z, acc[2][2]); acc[2][3] = fmaf(a.z, b.w, acc[2][3]);
            acc[3][0] = fmaf(a.w, b.x, acc[3][0]); acc[3][1] = fmaf(a.w, b.y, acc[3][1]);
            acc[3][2] = fmaf(a.w, b.z, acc[3][2]); acc[3][3] = fmaf(a.w, b.w, acc[3][3]);
        }
        __syncthreads();
    }

#pragma unroll
    for (int q = 0; q < 4; q++) {
        int idx = tid + 256 * q;
        int j = idx >> 4, i4 = (idx & 15) << 2;
        float4 t = *(const float4*)(ADJ + (size_t)(colBase + j) * NN + rowBase + i4);
        Ts[j][i4] = t.x; Ts[j][i4 + 1] = t.y; Ts[j][i4 + 2] = t.z; Ts[j][i4 + 3] = t.w;
    }
    __syncthreads();

    float term = 0.f;
    bool off = (bi != bj);
#pragma unroll
    for (int ii = 0; ii < 4; ii++) {
        int il = ty * 4 + ii;
        float4 ad = *(const float4*)(ADJ + (size_t)(rowBase + il) * NN + colBase + (tx << 2));
        float adv[4] = {ad.x, ad.y, ad.z, ad.w};
#pragma unroll
        for (int jj = 0; jj < 4; jj++) {
            int jl = (tx << 2) + jj;
            float c = acc[ii][jj];
            float sp = fmaxf(c, 0.f) + log1pf(expf(-fabsf(c)));  // stable softplus
            if (off || il < jl)      term += 2.f * sp - c * (adv[jj] + Ts[jl][il]);
            else if (il == jl)       term += sp - c * adv[jj];
        }
    }
    __shared__ float sred[256];
    sred[tid] = term; __syncthreads();
    for (int s = 128; s > 0; s >>= 1) {
        if (tid < s) sred[tid] += sred[tid + s];
        __syncthreads();
    }
    if (tid == 0) glpart[bi * LBLK + bj] = sred[0];
}

// ================= final reduction of partials -> loss scalar =================
__global__ void finalize_kernel(const float* __restrict__ klpart,
                                const float* __restrict__ glpart,
                                float* __restrict__ outScalar) {
    __shared__ double sk[256], sg[256];
    int t = threadIdx.x;
    double a = 0.0, b = 0.0;
    for (int i = t; i < 512; i += 256)          a += (double)klpart[i];
    for (int i = t; i < LBLK * LBLK; i += 256)  b += (double)glpart[i];
    sk[t] = a; sg[t] = b; __syncthreads();
    for (int s = 128; s > 0; s >>= 1) {
        if (t < s) { sk[t] += sk[t + s]; sg[t] += sg[t + s]; }
        __syncthreads();
    }
    if (t == 0) {
        double kl = -0.5 * sk[0] / (double)NN;
        double gl = sg[0] / ((double)NN * (double)NN);
        *outScalar = (float)(kl + gl);
    }
}

// ================= host launcher: ONLY kernel launches =================
extern "C" void kernel_launch(void* const* d_in, const int* in_sizes, int n_in,
                              void* d_out, int out_size) {
    const float* enc = (const float*)d_in[0];
    const int*   ei  = (const int*)d_in[1];    // int32 edge_index [2, E]
    const float* w   = (const float*)d_in[2];
    const float* ADJ = (const float*)d_in[3];
    const float* eps = (const float*)d_in[4];
    const float* W1 = (const float*)d_in[5];  const float* b1 = (const float*)d_in[6];
    const float* W2 = (const float*)d_in[7];  const float* b2 = (const float*)d_in[8];
    const float* W3 = (const float*)d_in[9];  const float* b3 = (const float*)d_in[10];
    const float* W4 = (const float*)d_in[11]; const float* b4 = (const float*)d_in[12];

    float* out  = (float*)d_out;
    float* enc2 = out;                        // [N, D] output region
    float* zreg = out + (size_t)NN * DD;      // [N, K, D] output region = scratch arena

    // scratch views inside the Z region (all dead before the final Z write)
    int*   deg  = (int*)  (zreg + S_DEG);
    int*   off  = (int*)  (zreg + S_OFF);
    int*   cur  = (int*)  (zreg + S_CUR);
    int*   esrc = (int*)  (zreg + S_ESRC);
    float* ew   =          zreg + S_EW;
    float* hcat =          zreg + S_HCAT;
    float* h1   =          zreg + S_H1;
    float* Zl   =          zreg + S_ZL;
    float* klp  =          zreg + S_KLP;
    float* glp  =          zreg + S_GLP;
    float* outScalar = out + (size_t)out_size - 1;

    // CSR build (reused by both convs)
    zero_deg_kernel<<<NN / 256, 256>>>(deg);
    hist_kernel<<<EE / 256, 256>>>(ei, deg);
    scan_kernel<<<1, 256>>>(deg, off, cur);
    fill_kernel<<<EE / 256, 256>>>(ei, w, cur, esrc, ew);

    // conv1 + linear1 + relu
    gather_kernel<<<NN, 256>>>(enc, hcat, deg, off, esrc, ew);
    gemm_kernel<true, false, 512><<<dim3(4, 128), 256>>>(hcat, W1, b1, enc, h1);

    // conv2 + linear2 + relu + residual -> enc2 (output region)
    gather_kernel<<<NN, 256>>>(h1, hcat, deg, off, esrc, ew);
    gemm_kernel<true, true, 512><<<dim3(4, 128), 256>>>(hcat, W2, b2, enc, enc2);

    // fused heads -> Zl + KL partials (mu/lv recomputed in-register, never stored)
    heads_kernel<0><<<dim3(4, 128), 256>>>(enc2, W3, b3, W4, b4, eps, Zl, klp);

    // fused logits GEMM + BCE loss partials (symmetric half)
    loss_kernel<<<dim3(LBLK, LBLK), 256>>>(Zl, ADJ, glp);

    // loss scalar (before Z overwrites the partials)
    finalize_kernel<<<1, 256>>>(klp, glp, outScalar);

    // final: write Z over the whole scratch arena (reads only enc2/weights/eps)
    heads_kernel<1><<<dim3(4, 128), 256>>>(enc2, W3, b3, W4, b4, eps, zreg, klp);
}

// round 8
// speedup vs baseline: 1.0430x; 1.0430x over previous
#include <cuda_runtime.h>
#include <cuda_bf16.h>
#include <mma.h>
#include <math.h>
#include <stdint.h>

using namespace nvcuda;

#define NN 8192
#define DD 256
#define EE 262144
#define KK 8

// loss grid: 64 row-blocks (M=128) x 128 col-blocks (N=64)
#define LGY 64
#define LGX 128

// ---- scratch layout inside the Z region of d_out (16,777,216 floats) ----
#define S_DEG   0
#define S_OFF   8192
#define S_CUR   16384
#define S_ESRC  24576
#define S_EW    286720
#define S_HCAT  1048576
#define S_H1    5242880
#define S_ZLH   7340032                // Zl_hi bf16
#define S_ZLL   8388608                // Zl_lo bf16
#define S_KLP   9437184
#define S_GLP   9437696                // 8192 floats

// loss kernel smem: 4 panels, ld = 136 bf16 (K-chunk 128 + pad 8)
#define LDK 136
#define LOSS_SMEM (384 * LDK * 2)      // 104,448 bytes
#define LDC 72                          // fp32 C buffer leading dim

// ================= CSR build =================
__global__ void zero_deg_kernel(int* deg) {
    deg[blockIdx.x * 256 + threadIdx.x] = 0;
}
__global__ void hist_kernel(const int* __restrict__ ei, int* deg) {
    int e = blockIdx.x * 256 + threadIdx.x;
    atomicAdd(&deg[ei[EE + e]], 1);
}
__global__ void scan_kernel(const int* __restrict__ deg, int* off, int* cur) {
    __shared__ int s[256];
    int tid = threadIdx.x;
    int base = tid * 32;
    int loc[32];
    int sum = 0;
#pragma unroll
    for (int i = 0; i < 32; i++) { loc[i] = deg[base + i]; sum += loc[i]; }
    s[tid] = sum;
    __syncthreads();
    for (int o = 1; o < 256; o <<= 1) {
        int v = (tid >= o) ? s[tid - o] : 0;
        __syncthreads();
        s[tid] += v;
        __syncthreads();
    }
    int run = s[tid] - sum;
#pragma unroll
    for (int i = 0; i < 32; i++) {
        off[base + i] = run;
        cur[base + i] = run;
        run += loc[i];
    }
}
__global__ void fill_kernel(const int* __restrict__ ei, const float* __restrict__ w,
                            int* cur, int* esrc, float* ew) {
    int e = blockIdx.x * 256 + threadIdx.x;
    int src = ei[e];
    int dst = ei[EE + e];
    int slot = atomicAdd(&cur[dst], 1);
    esrc[slot] = src;
    ew[slot]   = w[e];
}

// ============ gather conv + fused combine ============
__global__ void gather_kernel(const float* __restrict__ x, float* __restrict__ hcat,
                              const int* __restrict__ deg, const int* __restrict__ off,
                              const int* __restrict__ esrc, const float* __restrict__ ew) {
    __shared__ int   ss[256];
    __shared__ float sw[256];
    int n = blockIdx.x, d = threadIdx.x;
    int beg = off[n];
    int dg  = deg[n];
    float acc = 0.f;
    for (int c = 0; c < dg; c += 256) {
        int m = min(256, dg - c);
        if (d < m) { ss[d] = esrc[beg + c + d]; sw[d] = ew[beg + c + d]; }
        __syncthreads();
#pragma unroll 4
        for (int j = 0; j < m; j++)
            acc = fmaf(x[(size_t)ss[j] * DD + d], sw[j], acc);
        __syncthreads();
    }
    hcat[n * 512 + d]       = x[(size_t)n * DD + d];
    hcat[n * 512 + 256 + d] = acc / fmaxf((float)dg, 1.f);
}

// ====== fp32 GEMM: C = act(A @ W + b) (+res) ======
template<bool RELU, bool RES, int KD>
__global__ void gemm_kernel(const float* __restrict__ A, const float* __restrict__ W,
                            const float* __restrict__ bias, const float* __restrict__ res,
                            float* __restrict__ C) {
    __shared__ __align__(16) float As[16][68];
    __shared__ __align__(16) float Bs[16][68];
    int tid = threadIdx.x;
    int tx = tid & 15, ty = tid >> 4;
    int rowBase = blockIdx.y * 64, colBase = blockIdx.x * 64;
    float acc[4][4];
#pragma unroll
    for (int i = 0; i < 4; i++)
#pragma unroll
        for (int j = 0; j < 4; j++) acc[i][j] = 0.f;

    int arow = tid >> 2, ac = tid & 3;
    int wk = tid >> 4, wj = (tid & 15) << 2;

    for (int k0 = 0; k0 < KD; k0 += 16) {
        float4 av = *(const float4*)(A + (size_t)(rowBase + arow) * KD + k0 + ac * 4);
        As[ac * 4 + 0][arow] = av.x; As[ac * 4 + 1][arow] = av.y;
        As[ac * 4 + 2][arow] = av.z; As[ac * 4 + 3][arow] = av.w;
        *(float4*)&Bs[wk][wj] = *(const float4*)(W + (size_t)(k0 + wk) * 256 + colBase + wj);
        __syncthreads();
#pragma unroll
        for (int k = 0; k < 16; k++) {
            float4 a = *(float4*)&As[k][ty * 4];
            float4 b = *(float4*)&Bs[k][tx * 4];
            acc[0][0] = fmaf(a.x, b.x, acc[0][0]); acc[0][1] = fmaf(a.x, b.y, acc[0][1]);
            acc[0][2] = fmaf(a.x, b.z, acc[0][2]); acc[0][3] = fmaf(a.x, b.w, acc[0][3]);
            acc[1][0] = fmaf(a.y, b.x, acc[1][0]); acc[1][1] = fmaf(a.y, b.y, acc[1][1]);
            acc[1][2] = fmaf(a.y, b.z, acc[1][2]); acc[1][3] = fmaf(a.y, b.w, acc[1][3]);
            acc[2][0] = fmaf(a.z, b.x, acc[2][0]); acc[2][1] = fmaf(a.z, b.y, acc[2][1]);
            acc[2][2] = fmaf(a.z, b.z, acc[2][2]); acc[2][3] = fmaf(a.z, b.w, acc[2][3]);
            acc[3][0] = fmaf(a.w, b.x, acc[3][0]); acc[3][1] = fmaf(a.w, b.y, acc[3][1]);
            acc[3][2] = fmaf(a.w, b.z, acc[3][2]); acc[3][3] = fmaf(a.w, b.w, acc[3][3]);
        }
        __syncthreads();
    }

    float4 bv = *(const float4*)(bias + colBase + tx * 4);
#pragma unroll
    for (int ii = 0; ii < 4; ii++) {
        int r = rowBase + ty * 4 + ii;
        float4 o;
        o.x = acc[ii][0] + bv.x; o.y = acc[ii][1] + bv.y;
        o.z = acc[ii][2] + bv.z; o.w = acc[ii][3] + bv.w;
        if (RELU) {
            o.x = fmaxf(o.x, 0.f); o.y = fmaxf(o.y, 0.f);
            o.z = fmaxf(o.z, 0.f); o.w = fmaxf(o.w, 0.f);
        }
        if (RES) {
            float4 rv = *(const float4*)(res + (size_t)r * 256 + colBase + (tx << 2));
            o.x += rv.x; o.y += rv.y; o.z += rv.z; o.w += rv.w;
        }
        *(float4*)(C + (size_t)r * 256 + colBase + (tx << 2)) = o;
    }
}

// ====== fused heads: mu/lv in-register from enc2@W3 / enc2@W4 ======
template<int MODE>
__global__ void heads_kernel(const float* __restrict__ enc2,
                             const float* __restrict__ W3, const float* __restrict__ b3,
                             const float* __restrict__ W4, const float* __restrict__ b4,
                             const float* __restrict__ eps,
                             float* __restrict__ dstZ,
                             __nv_bfloat16* __restrict__ zhi,
                             __nv_bfloat16* __restrict__ zlo,
                             float* __restrict__ klpart) {
    __shared__ __align__(16) float As[16][68];
    __shared__ __align__(16) float B3s[16][68];
    __shared__ __align__(16) float B4s[16][68];
    int tid = threadIdx.x;
    int tx = tid & 15, ty = tid >> 4;
    int rowBase = blockIdx.y * 64, colBase = blockIdx.x * 64;
    float am[4][4], al[4][4];
#pragma unroll
    for (int i = 0; i < 4; i++)
#pragma unroll
        for (int j = 0; j < 4; j++) { am[i][j] = 0.f; al[i][j] = 0.f; }

    int arow = tid >> 2, ac = tid & 3;
    int wk = tid >> 4, wj = (tid & 15) << 2;

    for (int k0 = 0; k0 < 256; k0 += 16) {
        float4 av = *(const float4*)(enc2 + (size_t)(rowBase + arow) * 256 + k0 + ac * 4);
        As[ac * 4 + 0][arow] = av.x; As[ac * 4 + 1][arow] = av.y;
        As[ac * 4 + 2][arow] = av.z; As[ac * 4 + 3][arow] = av.w;
        *(float4*)&B3s[wk][wj] = *(const float4*)(W3 + (size_t)(k0 + wk) * 256 + colBase + wj);
        *(float4*)&B4s[wk][wj] = *(const float4*)(W4 + (size_t)(k0 + wk) * 256 + colBase + wj);
        __syncthreads();
#pragma unroll
        for (int k = 0; k < 16; k++) {
            float4 a  = *(float4*)&As[k][ty * 4];
            float4 b3v = *(float4*)&B3s[k][tx * 4];
            float4 b4v = *(float4*)&B4s[k][tx * 4];
            float aa[4] = {a.x, a.y, a.z, a.w};
            float m3[4] = {b3v.x, b3v.y, b3v.z, b3v.w};
            float m4[4] = {b4v.x, b4v.y, b4v.z, b4v.w};
#pragma unroll
            for (int ii = 0; ii < 4; ii++)
#pragma unroll
                for (int jj = 0; jj < 4; jj++) {
                    am[ii][jj] = fmaf(aa[ii], m3[jj], am[ii][jj]);
                    al[ii][jj] = fmaf(aa[ii], m4[jj], al[ii][jj]);
                }
        }
        __syncthreads();
    }

    float4 bv3 = *(const float4*)(b3 + colBase + tx * 4);
    float4 bv4 = *(const float4*)(b4 + colBase + tx * 4);
    float bb3[4] = {bv3.x, bv3.y, bv3.z, bv3.w};
    float bb4[4] = {bv4.x, bv4.y, bv4.z, bv4.w};

    float klsum = 0.f;
#pragma unroll
    for (int ii = 0; ii < 4; ii++) {
        int n = rowBase + ty * 4 + ii;
        int col = colBase + (tx << 2);
        float mu[4], lv[4], sg[4];
#pragma unroll
        for (int jj = 0; jj < 4; jj++) {
            mu[jj] = am[ii][jj] + bb3[jj];
            lv[jj] = al[ii][jj] + bb4[jj];
            sg[jj] = expf(0.5f * lv[jj]);
        }
        if (MODE == 0) {
            float4 es = make_float4(0.f, 0.f, 0.f, 0.f);
#pragma unroll
            for (int k = 0; k < KK; k++) {
                float4 e = *(const float4*)(eps + (size_t)(n * KK + k) * DD + col);
                es.x += e.x; es.y += e.y; es.z += e.z; es.w += e.w;
            }
            float zv[4];
            zv[0] = fmaf(sg[0], es.x * 0.125f, mu[0]);
            zv[1] = fmaf(sg[1], es.y * 0.125f, mu[1]);
            zv[2] = fmaf(sg[2], es.z * 0.125f, mu[2]);
            zv[3] = fmaf(sg[3], es.w * 0.125f, mu[3]);
            __nv_bfloat16 h[4], l[4];
#pragma unroll
            for (int jj = 0; jj < 4; jj++) {
                h[jj] = __float2bfloat16(zv[jj]);
                l[jj] = __float2bfloat16(zv[jj] - __bfloat162float(h[jj]));
            }
            size_t base = (size_t)n * DD + col;
            *(__nv_bfloat162*)(zhi + base)     = __nv_bfloat162(h[0], h[1]);
            *(__nv_bfloat162*)(zhi + base + 2) = __nv_bfloat162(h[2], h[3]);
            *(__nv_bfloat162*)(zlo + base)     = __nv_bfloat162(l[0], l[1]);
            *(__nv_bfloat162*)(zlo + base + 2) = __nv_bfloat162(l[2], l[3]);
#pragma unroll
            for (int jj = 0; jj < 4; jj++)
                klsum += 1.f + lv[jj] - mu[jj] * mu[jj] - sg[jj] * sg[jj];
        } else {
#pragma unroll
            for (int k = 0; k < KK; k++) {
                float4 e = *(const float4*)(eps + (size_t)(n * KK + k) * DD + col);
                float4 o;
                o.x = fmaf(sg[0], e.x, mu[0]);
                o.y = fmaf(sg[1], e.y, mu[1]);
                o.z = fmaf(sg[2], e.z, mu[2]);
                o.w = fmaf(sg[3], e.w, mu[3]);
                *(float4*)(dstZ + (size_t)(n * KK + k) * DD + col) = o;
            }
        }
    }

    if (MODE == 0) {
        __shared__ float sred[256];
        sred[tid] = klsum; __syncthreads();
        for (int s = 128; s > 0; s >>= 1) {
            if (tid < s) sred[tid] += sred[tid + s];
            __syncthreads();
        }
        if (tid == 0) klpart[blockIdx.y * 4 + blockIdx.x] = sred[0];
    }
}

// ====== WMMA bf16 loss: 3-split Zl@Zl^T + BCE, M=128 x N=64 tiles ======
__global__ void __launch_bounds__(256, 2) loss_mma_kernel(
    const __nv_bfloat16* __restrict__ zhi, const __nv_bfloat16* __restrict__ zlo,
    const float* __restrict__ ADJ, float* __restrict__ glpart) {
    int bi = blockIdx.y, bj = blockIdx.x;
    int tid = threadIdx.x;
    int rowBase = bi * 128, colBase = bj * 64;

    if (colBase + 64 <= rowBase) {               // entirely below diagonal
        if (tid == 0) glpart[bi * LGX + bj] = 0.f;
        return;
    }

    extern __shared__ __align__(16) char smc[];
    __nv_bfloat16* AH = (__nv_bfloat16*)smc;                 // 128 x LDK
    __nv_bfloat16* AL = AH + 128 * LDK;                      // 128 x LDK
    __nv_bfloat16* BH = AL + 128 * LDK;                      // 64 x LDK
    __nv_bfloat16* BL = BH + 64 * LDK;                       // 64 x LDK

    int wid = tid >> 5;
    int wm0 = (wid >> 1) * 32;      // warp row offset (0,32,64,96)
    int wn0 = (wid & 1) * 32;       // warp col offset (0,32)

    wmma::fragment<wmma::accumulator, 16, 16, 16, float> acc[2][2];
#pragma unroll
    for (int m = 0; m < 2; m++)
#pragma unroll
        for (int n = 0; n < 2; n++) wmma::fill_fragment(acc[m][n], 0.f);

    for (int kc = 0; kc < 2; kc++) {
        int kg = kc * 128;
        // load A panels: 128 rows x 16 uint4 each
        for (int idx = tid; idx < 128 * 16; idx += 256) {
            int r = idx >> 4, c8 = (idx & 15) << 3;
            size_t g = (size_t)(rowBase + r) * 256 + kg + c8;
            *(uint4*)&AH[r * LDK + c8] = *(const uint4*)(zhi + g);
            *(uint4*)&AL[r * LDK + c8] = *(const uint4*)(zlo + g);
        }
        // load B panels: 64 rows x 16 uint4 each
        for (int idx = tid; idx < 64 * 16; idx += 256) {
            int r = idx >> 4, c8 = (idx & 15) << 3;
            size_t g = (size_t)(colBase + r) * 256 + kg + c8;
            *(uint4*)&BH[r * LDK + c8] = *(const uint4*)(zhi + g);
            *(uint4*)&BL[r * LDK + c8] = *(const uint4*)(zlo + g);
        }
        __syncthreads();

#pragma unroll
        for (int ks = 0; ks < 8; ks++) {
            int k0 = ks * 16;
            wmma::fragment<wmma::matrix_a, 16, 16, 16, __nv_bfloat16, wmma::row_major> aH[2], aL[2];
            wmma::fragment<wmma::matrix_b, 16, 16, 16, __nv_bfloat16, wmma::col_major> bH[2], bL[2];
#pragma unroll
            for (int m = 0; m < 2; m++) {
                wmma::load_matrix_sync(aH[m], &AH[(wm0 + m * 16) * LDK + k0], LDK);
                wmma::load_matrix_sync(aL[m], &AL[(wm0 + m * 16) * LDK + k0], LDK);
            }
#pragma unroll
            for (int n = 0; n < 2; n++) {
                wmma::load_matrix_sync(bH[n], &BH[(wn0 + n * 16) * LDK + k0], LDK);
                wmma::load_matrix_sync(bL[n], &BL[(wn0 + n * 16) * LDK + k0], LDK);
            }
#pragma unroll
            for (int m = 0; m < 2; m++)
#pragma unroll
                for (int n = 0; n < 2; n++) {
                    wmma::mma_sync(acc[m][n], aH[m], bH[n], acc[m][n]);
                    wmma::mma_sync(acc[m][n], aH[m], bL[n], acc[m][n]);
                    wmma::mma_sync(acc[m][n], aL[m], bH[n], acc[m][n]);
                }
        }
        __syncthreads();
    }

    // ---- store C to smem (reuse A region: 128 x LDC fp32 = 36,864B < 2*LDK panel) ----
    float* Cs = (float*)smc;
#pragma unroll
    for (int m = 0; m < 2; m++)
#pragma unroll
        for (int n = 0; n < 2; n++)
            wmma::store_matrix_sync(&Cs[(wm0 + m * 16) * LDC + wn0 + n * 16],
                                    acc[m][n], LDC, wmma::mem_row_major);
    __syncthreads();

    // ---- BCE epilogue ----
    float term = 0.f;
    // loop1: i<=j terms, lanes across j (ADJ row-coalesced)
    {
        int jl = tid & 63;
        int j = colBase + jl;
        for (int il = tid >> 6; il < 128; il += 4) {
            int i = rowBase + il;
            if (i > j) continue;
            float c = Cs[il * LDC + jl];
            float sp = fmaxf(c, 0.f) + log1pf(expf(-fabsf(c)));
            float a = ADJ[(size_t)i * NN + j];
            term += (i < j ? 2.f : 1.f) * sp - c * a;
        }
    }
    // loop2: i<j transposed term, lanes across i (ADJ row-coalesced)
    {
        int ilane = tid & 63;
        for (int jl = tid >> 6; jl < 64; jl += 4) {
            int j = colBase + jl;
#pragma unroll
            for (int ib = 0; ib < 128; ib += 64) {
                int il = ib + ilane;
                int i = rowBase + il;
                if (i < j)
                    term -= Cs[il * LDC + jl] * ADJ[(size_t)j * NN + i];
            }
        }
    }

    __shared__ float sred[256];
    sred[tid] = term; __syncthreads();
    for (int s = 128; s > 0; s >>= 1) {
        if (tid < s) sred[tid] += sred[tid + s];
        __syncthreads();
    }
    if (tid == 0) glpart[bi * LGX + bj] = sred[0];
}

// ================= final reduction =================
__global__ void finalize_kernel(const float* __restrict__ klpart,
                                const float* __restrict__ glpart,
                                float* __restrict__ outScalar) {
    __shared__ double sk[256], sg[256];
    int t = threadIdx.x;
    double a = 0.0, b = 0.0;
    for (int i = t; i < 512; i += 256)           a += (double)klpart[i];
    for (int i = t; i < LGY * LGX; i += 256)     b += (double)glpart[i];
    sk[t] = a; sg[t] = b; __syncthreads();
    for (int s = 128; s > 0; s >>= 1) {
        if (t < s) { sk[t] += sk[t + s]; sg[t] += sg[t + s]; }
        __syncthreads();
    }
    if (t == 0) {
        double kl = -0.5 * sk[0] / (double)NN;
        double gl = sg[0] / ((double)NN * (double)NN);
        *outScalar = (float)(kl + gl);
    }
}

// ================= host launcher =================
extern "C" void kernel_launch(void* const* d_in, const int* in_sizes, int n_in,
                              void* d_out, int out_size) {
    const float* enc = (const float*)d_in[0];
    const int*   ei  = (const int*)d_in[1];
    const float* w   = (const float*)d_in[2];
    const float* ADJ = (const float*)d_in[3];
    const float* eps = (const float*)d_in[4];
    const float* W1 = (const float*)d_in[5];  const float* b1 = (const float*)d_in[6];
    const float* W2 = (const float*)d_in[7];  const float* b2 = (const float*)d_in[8];
    const float* W3 = (const float*)d_in[9];  const float* b3 = (const float*)d_in[10];
    const float* W4 = (const float*)d_in[11]; const float* b4 = (const float*)d_in[12];

    float* out  = (float*)d_out;
    float* enc2 = out;
    float* zreg = out + (size_t)NN * DD;

    int*   deg  = (int*)  (zreg + S_DEG);
    int*   off  = (int*)  (zreg + S_OFF);
    int*   cur  = (int*)  (zreg + S_CUR);
    int*   esrc = (int*)  (zreg + S_ESRC);
    float* ew   =          zreg + S_EW;
    float* hcat =          zreg + S_HCAT;
    float* h1   =          zreg + S_H1;
    __nv_bfloat16* zhi = (__nv_bfloat16*)(zreg + S_ZLH);
    __nv_bfloat16* zlo = (__nv_bfloat16*)(zreg + S_ZLL);
    float* klp  =          zreg + S_KLP;
    float* glp  =          zreg + S_GLP;
    float* outScalar = out + (size_t)out_size - 1;

    cudaFuncSetAttribute(loss_mma_kernel,
                         cudaFuncAttributeMaxDynamicSharedMemorySize, LOSS_SMEM);

    // CSR build
    zero_deg_kernel<<<NN / 256, 256>>>(deg);
    hist_kernel<<<EE / 256, 256>>>(ei, deg);
    scan_kernel<<<1, 256>>>(deg, off, cur);
    fill_kernel<<<EE / 256, 256>>>(ei, w, cur, esrc, ew);

    // conv1 + linear1 + relu
    gather_kernel<<<NN, 256>>>(enc, hcat, deg, off, esrc, ew);
    gemm_kernel<true, false, 512><<<dim3(4, 128), 256>>>(hcat, W1, b1, enc, h1);

    // conv2 + linear2 + relu + residual -> enc2
    gather_kernel<<<NN, 256>>>(h1, hcat, deg, off, esrc, ew);
    gemm_kernel<true, true, 512><<<dim3(4, 128), 256>>>(hcat, W2, b2, enc, enc2);

    // fused heads -> Zl split-bf16 + KL partials
    heads_kernel<0><<<dim3(4, 128), 256>>>(enc2, W3, b3, W4, b4, eps,
                                           nullptr, zhi, zlo, klp);

    // WMMA loss GEMM + BCE
    loss_mma_kernel<<<dim3(LGX, LGY), 256, LOSS_SMEM>>>(zhi, zlo, ADJ, glp);

    // loss scalar before Z overwrites partials
    finalize_kernel<<<1, 256>>>(klp, glp, outScalar);

    // final: write Z over the scratch arena
    heads_kernel<1><<<dim3(4, 128), 256>>>(enc2, W3, b3, W4, b4, eps,
                                           zreg, nullptr, nullptr, nullptr);
}

// round 9
// speedup vs baseline: 1.1525x; 1.1049x over previous
#include <cuda_runtime.h>
#include <cuda_bf16.h>
#include <mma.h>
#include <math.h>
#include <stdint.h>

using namespace nvcuda;

#define NN 8192
#define DD 256
#define EE 262144
#define KK 8

// loss grid: 64 row-blocks (M=128) x 128 col-blocks (N=64)
#define LGY 64
#define LGX 128

// ---- scratch layout inside the Z region of d_out (16,777,216 floats) ----
#define S_DEG   0
#define S_OFF   8192
#define S_CUR   16384
#define S_ESRC  24576
#define S_EW    286720
#define S_HCAT  1048576
#define S_H1    5242880
#define S_ZLH   7340032                // Zl_hi bf16
#define S_KLP   9437184
#define S_GLP   9437696                // 8192 floats

// loss kernel smem: 2 panels (A:128, B:64 rows), ld = 136 bf16
#define LDK 136
#define LOSS_SMEM (192 * LDK * 2)      // 52,224 bytes
#define LDC 72                          // fp32 C buffer leading dim

// ================= CSR build =================
__global__ void zero_deg_kernel(int* deg) {
    deg[blockIdx.x * 256 + threadIdx.x] = 0;
}
__global__ void hist_kernel(const int* __restrict__ ei, int* deg) {
    int e = blockIdx.x * 256 + threadIdx.x;
    atomicAdd(&deg[ei[EE + e]], 1);
}
__global__ void scan_kernel(const int* __restrict__ deg, int* off, int* cur) {
    __shared__ int s[256];
    int tid = threadIdx.x;
    int base = tid * 32;
    int loc[32];
    int sum = 0;
#pragma unroll
    for (int i = 0; i < 32; i++) { loc[i] = deg[base + i]; sum += loc[i]; }
    s[tid] = sum;
    __syncthreads();
    for (int o = 1; o < 256; o <<= 1) {
        int v = (tid >= o) ? s[tid - o] : 0;
        __syncthreads();
        s[tid] += v;
        __syncthreads();
    }
    int run = s[tid] - sum;
#pragma unroll
    for (int i = 0; i < 32; i++) {
        off[base + i] = run;
        cur[base + i] = run;
        run += loc[i];
    }
}
__global__ void fill_kernel(const int* __restrict__ ei, const float* __restrict__ w,
                            int* cur, int* esrc, float* ew) {
    int e = blockIdx.x * 256 + threadIdx.x;
    int src = ei[e];
    int dst = ei[EE + e];
    int slot = atomicAdd(&cur[dst], 1);
    esrc[slot] = src;
    ew[slot]   = w[e];
}

// ============ gather conv + fused combine ============
__global__ void gather_kernel(const float* __restrict__ x, float* __restrict__ hcat,
                              const int* __restrict__ deg, const int* __restrict__ off,
                              const int* __restrict__ esrc, const float* __restrict__ ew) {
    __shared__ int   ss[256];
    __shared__ float sw[256];
    int n = blockIdx.x, d = threadIdx.x;
    int beg = off[n];
    int dg  = deg[n];
    float acc = 0.f;
    for (int c = 0; c < dg; c += 256) {
        int m = min(256, dg - c);
        if (d < m) { ss[d] = esrc[beg + c + d]; sw[d] = ew[beg + c + d]; }
        __syncthreads();
#pragma unroll 4
        for (int j = 0; j < m; j++)
            acc = fmaf(x[(size_t)ss[j] * DD + d], sw[j], acc);
        __syncthreads();
    }
    hcat[n * 512 + d]       = x[(size_t)n * DD + d];
    hcat[n * 512 + 256 + d] = acc / fmaxf((float)dg, 1.f);
}

// ====== fp32 GEMM: C = act(A @ W + b) (+res) ======
template<bool RELU, bool RES, int KD>
__global__ void gemm_kernel(const float* __restrict__ A, const float* __restrict__ W,
                            const float* __restrict__ bias, const float* __restrict__ res,
                            float* __restrict__ C) {
    __shared__ __align__(16) float As[16][68];
    __shared__ __align__(16) float Bs[16][68];
    int tid = threadIdx.x;
    int tx = tid & 15, ty = tid >> 4;
    int rowBase = blockIdx.y * 64, colBase = blockIdx.x * 64;
    float acc[4][4];
#pragma unroll
    for (int i = 0; i < 4; i++)
#pragma unroll
        for (int j = 0; j < 4; j++) acc[i][j] = 0.f;

    int arow = tid >> 2, ac = tid & 3;
    int wk = tid >> 4, wj = (tid & 15) << 2;

    for (int k0 = 0; k0 < KD; k0 += 16) {
        float4 av = *(const float4*)(A + (size_t)(rowBase + arow) * KD + k0 + ac * 4);
        As[ac * 4 + 0][arow] = av.x; As[ac * 4 + 1][arow] = av.y;
        As[ac * 4 + 2][arow] = av.z; As[ac * 4 + 3][arow] = av.w;
        *(float4*)&Bs[wk][wj] = *(const float4*)(W + (size_t)(k0 + wk) * 256 + colBase + wj);
        __syncthreads();
#pragma unroll
        for (int k = 0; k < 16; k++) {
            float4 a = *(float4*)&As[k][ty * 4];
            float4 b = *(float4*)&Bs[k][tx * 4];
            acc[0][0] = fmaf(a.x, b.x, acc[0][0]); acc[0][1] = fmaf(a.x, b.y, acc[0][1]);
            acc[0][2] = fmaf(a.x, b.z, acc[0][2]); acc[0][3] = fmaf(a.x, b.w, acc[0][3]);
            acc[1][0] = fmaf(a.y, b.x, acc[1][0]); acc[1][1] = fmaf(a.y, b.y, acc[1][1]);
            acc[1][2] = fmaf(a.y, b.z, acc[1][2]); acc[1][3] = fmaf(a.y, b.w, acc[1][3]);
            acc[2][0] = fmaf(a.z, b.x, acc[2][0]); acc[2][1] = fmaf(a.z, b.y, acc[2][1]);
            acc[2][2] = fmaf(a.z, b.z, acc[2][2]); acc[2][3] = fmaf(a.z, b.w, acc[2][3]);
            acc[3][0] = fmaf(a.w, b.x, acc[3][0]); acc[3][1] = fmaf(a.w, b.y, acc[3][1]);
            acc[3][2] = fmaf(a.w, b.z, acc[3][2]); acc[3][3] = fmaf(a.w, b.w, acc[3][3]);
        }
        __syncthreads();
    }

    float4 bv = *(const float4*)(bias + colBase + tx * 4);
#pragma unroll
    for (int ii = 0; ii < 4; ii++) {
        int r = rowBase + ty * 4 + ii;
        float4 o;
        o.x = acc[ii][0] + bv.x; o.y = acc[ii][1] + bv.y;
        o.z = acc[ii][2] + bv.z; o.w = acc[ii][3] + bv.w;
        if (RELU) {
            o.x = fmaxf(o.x, 0.f); o.y = fmaxf(o.y, 0.f);
            o.z = fmaxf(o.z, 0.f); o.w = fmaxf(o.w, 0.f);
        }
        if (RES) {
            float4 rv = *(const float4*)(res + (size_t)r * 256 + colBase + (tx << 2));
            o.x += rv.x; o.y += rv.y; o.z += rv.z; o.w += rv.w;
        }
        *(float4*)(C + (size_t)r * 256 + colBase + (tx << 2)) = o;
    }
}

// ====== fused heads: mu/lv in-register from enc2@W3 / enc2@W4 ======
template<int MODE>
__global__ void heads_kernel(const float* __restrict__ enc2,
                             const float* __restrict__ W3, const float* __restrict__ b3,
                             const float* __restrict__ W4, const float* __restrict__ b4,
                             const float* __restrict__ eps,
                             float* __restrict__ dstZ,
                             __nv_bfloat16* __restrict__ zhi,
                             float* __restrict__ klpart) {
    __shared__ __align__(16) float As[16][68];
    __shared__ __align__(16) float B3s[16][68];
    __shared__ __align__(16) float B4s[16][68];
    int tid = threadIdx.x;
    int tx = tid & 15, ty = tid >> 4;
    int rowBase = blockIdx.y * 64, colBase = blockIdx.x * 64;
    float am[4][4], al[4][4];
#pragma unroll
    for (int i = 0; i < 4; i++)
#pragma unroll
        for (int j = 0; j < 4; j++) { am[i][j] = 0.f; al[i][j] = 0.f; }

    int arow = tid >> 2, ac = tid & 3;
    int wk = tid >> 4, wj = (tid & 15) << 2;

    for (int k0 = 0; k0 < 256; k0 += 16) {
        float4 av = *(const float4*)(enc2 + (size_t)(rowBase + arow) * 256 + k0 + ac * 4);
        As[ac * 4 + 0][arow] = av.x; As[ac * 4 + 1][arow] = av.y;
        As[ac * 4 + 2][arow] = av.z; As[ac * 4 + 3][arow] = av.w;
        *(float4*)&B3s[wk][wj] = *(const float4*)(W3 + (size_t)(k0 + wk) * 256 + colBase + wj);
        *(float4*)&B4s[wk][wj] = *(const float4*)(W4 + (size_t)(k0 + wk) * 256 + colBase + wj);
        __syncthreads();
#pragma unroll
        for (int k = 0; k < 16; k++) {
            float4 a  = *(float4*)&As[k][ty * 4];
            float4 b3v = *(float4*)&B3s[k][tx * 4];
            float4 b4v = *(float4*)&B4s[k][tx * 4];
            float aa[4] = {a.x, a.y, a.z, a.w};
            float m3[4] = {b3v.x, b3v.y, b3v.z, b3v.w};
            float m4[4] = {b4v.x, b4v.y, b4v.z, b4v.w};
#pragma unroll
            for (int ii = 0; ii < 4; ii++)
#pragma unroll
                for (int jj = 0; jj < 4; jj++) {
                    am[ii][jj] = fmaf(aa[ii], m3[jj], am[ii][jj]);
                    al[ii][jj] = fmaf(aa[ii], m4[jj], al[ii][jj]);
                }
        }
        __syncthreads();
    }

    float4 bv3 = *(const float4*)(b3 + colBase + tx * 4);
    float4 bv4 = *(const float4*)(b4 + colBase + tx * 4);
    float bb3[4] = {bv3.x, bv3.y, bv3.z, bv3.w};
    float bb4[4] = {bv4.x, bv4.y, bv4.z, bv4.w};

    float klsum = 0.f;
#pragma unroll
    for (int ii = 0; ii < 4; ii++) {
        int n = rowBase + ty * 4 + ii;
        int col = colBase + (tx << 2);
        float mu[4], lv[4], sg[4];
#pragma unroll
        for (int jj = 0; jj < 4; jj++) {
            mu[jj] = am[ii][jj] + bb3[jj];
            lv[jj] = al[ii][jj] + bb4[jj];
            sg[jj] = expf(0.5f * lv[jj]);
        }
        if (MODE == 0) {
            float4 es = make_float4(0.f, 0.f, 0.f, 0.f);
#pragma unroll
            for (int k = 0; k < KK; k++) {
                float4 e = *(const float4*)(eps + (size_t)(n * KK + k) * DD + col);
                es.x += e.x; es.y += e.y; es.z += e.z; es.w += e.w;
            }
            float zv[4];
            zv[0] = fmaf(sg[0], es.x * 0.125f, mu[0]);
            zv[1] = fmaf(sg[1], es.y * 0.125f, mu[1]);
            zv[2] = fmaf(sg[2], es.z * 0.125f, mu[2]);
            zv[3] = fmaf(sg[3], es.w * 0.125f, mu[3]);
            __nv_bfloat16 h[4];
#pragma unroll
            for (int jj = 0; jj < 4; jj++) h[jj] = __float2bfloat16(zv[jj]);
            size_t base = (size_t)n * DD + col;
            *(__nv_bfloat162*)(zhi + base)     = __nv_bfloat162(h[0], h[1]);
            *(__nv_bfloat162*)(zhi + base + 2) = __nv_bfloat162(h[2], h[3]);
#pragma unroll
            for (int jj = 0; jj < 4; jj++)
                klsum += 1.f + lv[jj] - mu[jj] * mu[jj] - sg[jj] * sg[jj];
        } else {
#pragma unroll
            for (int k = 0; k < KK; k++) {
                float4 e = *(const float4*)(eps + (size_t)(n * KK + k) * DD + col);
                float4 o;
                o.x = fmaf(sg[0], e.x, mu[0]);
                o.y = fmaf(sg[1], e.y, mu[1]);
                o.z = fmaf(sg[2], e.z, mu[2]);
                o.w = fmaf(sg[3], e.w, mu[3]);
                *(float4*)(dstZ + (size_t)(n * KK + k) * DD + col) = o;
            }
        }
    }

    if (MODE == 0) {
        __shared__ float sred[256];
        sred[tid] = klsum; __syncthreads();
        for (int s = 128; s > 0; s >>= 1) {
            if (tid < s) sred[tid] += sred[tid + s];
            __syncthreads();
        }
        if (tid == 0) klpart[blockIdx.y * 4 + blockIdx.x] = sred[0];
    }
}

// ====== WMMA bf16 loss: single-pass Zl@Zl^T + BCE, M=128 x N=64 tiles ======
__global__ void __launch_bounds__(256, 2) loss_mma_kernel(
    const __nv_bfloat16* __restrict__ zhi,
    const float* __restrict__ ADJ, float* __restrict__ glpart) {
    int bi = blockIdx.y, bj = blockIdx.x;
    int tid = threadIdx.x;
    int rowBase = bi * 128, colBase = bj * 64;

    if (colBase + 64 <= rowBase) {               // entirely below diagonal
        if (tid == 0) glpart[bi * LGX + bj] = 0.f;
        return;
    }

    extern __shared__ __align__(16) char smc[];
    __nv_bfloat16* AH = (__nv_bfloat16*)smc;                 // 128 x LDK
    __nv_bfloat16* BH = AH + 128 * LDK;                      // 64 x LDK

    int wid = tid >> 5;
    int wm0 = (wid >> 1) * 32;      // warp row offset (0,32,64,96)
    int wn0 = (wid & 1) * 32;       // warp col offset (0,32)

    wmma::fragment<wmma::accumulator, 16, 16, 16, float> acc[2][2];
#pragma unroll
    for (int m = 0; m < 2; m++)
#pragma unroll
        for (int n = 0; n < 2; n++) wmma::fill_fragment(acc[m][n], 0.f);

    for (int kc = 0; kc < 2; kc++) {
        int kg = kc * 128;
        for (int idx = tid; idx < 128 * 16; idx += 256) {
            int r = idx >> 4, c8 = (idx & 15) << 3;
            *(uint4*)&AH[r * LDK + c8] =
                *(const uint4*)(zhi + (size_t)(rowBase + r) * 256 + kg + c8);
        }
        for (int idx = tid; idx < 64 * 16; idx += 256) {
            int r = idx >> 4, c8 = (idx & 15) << 3;
            *(uint4*)&BH[r * LDK + c8] =
                *(const uint4*)(zhi + (size_t)(colBase + r) * 256 + kg + c8);
        }
        __syncthreads();

#pragma unroll
        for (int ks = 0; ks < 8; ks++) {
            int k0 = ks * 16;
            wmma::fragment<wmma::matrix_a, 16, 16, 16, __nv_bfloat16, wmma::row_major> aH[2];
            wmma::fragment<wmma::matrix_b, 16, 16, 16, __nv_bfloat16, wmma::col_major> bH[2];
#pragma unroll
            for (int m = 0; m < 2; m++)
                wmma::load_matrix_sync(aH[m], &AH[(wm0 + m * 16) * LDK + k0], LDK);
#pragma unroll
            for (int n = 0; n < 2; n++)
                wmma::load_matrix_sync(bH[n], &BH[(wn0 + n * 16) * LDK + k0], LDK);
#pragma unroll
            for (int m = 0; m < 2; m++)
#pragma unroll
                for (int n = 0; n < 2; n++)
                    wmma::mma_sync(acc[m][n], aH[m], bH[n], acc[m][n]);
        }
        __syncthreads();
    }

    // ---- store C to smem (reuse panel region: 128 x LDC fp32 = 36,864B) ----
    float* Cs = (float*)smc;
#pragma unroll
    for (int m = 0; m < 2; m++)
#pragma unroll
        for (int n = 0; n < 2; n++)
            wmma::store_matrix_sync(&Cs[(wm0 + m * 16) * LDC + wn0 + n * 16],
                                    acc[m][n], LDC, wmma::mem_row_major);
    __syncthreads();

    // ---- BCE epilogue ----
    float term = 0.f;
    {
        int jl = tid & 63;
        int j = colBase + jl;
        for (int il = tid >> 6; il < 128; il += 4) {
            int i = rowBase + il;
            if (i > j) continue;
            float c = Cs[il * LDC + jl];
            float sp = fmaxf(c, 0.f) + log1pf(expf(-fabsf(c)));
            float a = ADJ[(size_t)i * NN + j];
            term += (i < j ? 2.f : 1.f) * sp - c * a;
        }
    }
    {
        int ilane = tid & 63;
        for (int jl = tid >> 6; jl < 64; jl += 4) {
            int j = colBase + jl;
#pragma unroll
            for (int ib = 0; ib < 128; ib += 64) {
                int il = ib + ilane;
                int i = rowBase + il;
                if (i < j)
                    term -= Cs[il * LDC + jl] * ADJ[(size_t)j * NN + i];
            }
        }
    }

    __shared__ float sred[256];
    sred[tid] = term; __syncthreads();
    for (int s = 128; s > 0; s >>= 1) {
        if (tid < s) sred[tid] += sred[tid + s];
        __syncthreads();
    }
    if (tid == 0) glpart[bi * LGX + bj] = sred[0];
}

// ================= final reduction =================
__global__ void finalize_kernel(const float* __restrict__ klpart,
                                const float* __restrict__ glpart,
                                float* __restrict__ outScalar) {
    __shared__ double sk[256], sg[256];
    int t = threadIdx.x;
    double a = 0.0, b = 0.0;
    for (int i = t; i < 512; i += 256)           a += (double)klpart[i];
    for (int i = t; i < LGY * LGX; i += 256)     b += (double)glpart[i];
    sk[t] = a; sg[t] = b; __syncthreads();
    for (int s = 128; s > 0; s >>= 1) {
        if (t < s) { sk[t] += sk[t + s]; sg[t] += sg[t + s]; }
        __syncthreads();
    }
    if (t == 0) {
        double kl = -0.5 * sk[0] / (double)NN;
        double gl = sg[0] / ((double)NN * (double)NN);
        *outScalar = (float)(kl + gl);
    }
}

// ================= host launcher =================
extern "C" void kernel_launch(void* const* d_in, const int* in_sizes, int n_in,
                              void* d_out, int out_size) {
    const float* enc = (const float*)d_in[0];
    const int*   ei  = (const int*)d_in[1];
    const float* w   = (const float*)d_in[2];
    const float* ADJ = (const float*)d_in[3];
    const float* eps = (const float*)d_in[4];
    const float* W1 = (const float*)d_in[5];  const float* b1 = (const float*)d_in[6];
    const float* W2 = (const float*)d_in[7];  const float* b2 = (const float*)d_in[8];
    const float* W3 = (const float*)d_in[9];  const float* b3 = (const float*)d_in[10];
    const float* W4 = (const float*)d_in[11]; const float* b4 = (const float*)d_in[12];

    float* out  = (float*)d_out;
    float* enc2 = out;
    float* zreg = out + (size_t)NN * DD;

    int*   deg  = (int*)  (zreg + S_DEG);
    int*   off  = (int*)  (zreg + S_OFF);
    int*   cur  = (int*)  (zreg + S_CUR);
    int*   esrc = (int*)  (zreg + S_ESRC);
    float* ew   =          zreg + S_EW;
    float* hcat =          zreg + S_HCAT;
    float* h1   =          zreg + S_H1;
    __nv_bfloat16* zhi = (__nv_bfloat16*)(zreg + S_ZLH);
    float* klp  =          zreg + S_KLP;
    float* glp  =          zreg + S_GLP;
    float* outScalar = out + (size_t)out_size - 1;

    cudaFuncSetAttribute(loss_mma_kernel,
                         cudaFuncAttributeMaxDynamicSharedMemorySize, LOSS_SMEM);

    // CSR build
    zero_deg_kernel<<<NN / 256, 256>>>(deg);
    hist_kernel<<<EE / 256, 256>>>(ei, deg);
    scan_kernel<<<1, 256>>>(deg, off, cur);
    fill_kernel<<<EE / 256, 256>>>(ei, w, cur, esrc, ew);

    // conv1 + linear1 + relu
    gather_kernel<<<NN, 256>>>(enc, hcat, deg, off, esrc, ew);
    gemm_kernel<true, false, 512><<<dim3(4, 128), 256>>>(hcat, W1, b1, enc, h1);

    // conv2 + linear2 + relu + residual -> enc2
    gather_kernel<<<NN, 256>>>(h1, hcat, deg, off, esrc, ew);
    gemm_kernel<true, true, 512><<<dim3(4, 128), 256>>>(hcat, W2, b2, enc, enc2);

    // fused heads -> Zl bf16 + KL partials
    heads_kernel<0><<<dim3(4, 128), 256>>>(enc2, W3, b3, W4, b4, eps,
                                           nullptr, zhi, klp);

    // WMMA loss GEMM + BCE (single-pass bf16)
    loss_mma_kernel<<<dim3(LGX, LGY), 256, LOSS_SMEM>>>(zhi, ADJ, glp);

    // loss scalar before Z overwrites partials
    finalize_kernel<<<1, 256>>>(klp, glp, outScalar);

    // final: write Z over the scratch arena
    heads_kernel<1><<<dim3(4, 128), 256>>>(enc2, W3, b3, W4, b4, eps,
                                           zreg, nullptr, nullptr);
}

// round 10
// speedup vs baseline: 1.3362x; 1.1594x over previous
#include <cuda_runtime.h>
#include <cuda_bf16.h>
#include <mma.h>
#include <math.h>
#include <stdint.h>

using namespace nvcuda;

#define NN 8192
#define DD 256
#define EE 262144
#define KK 8

#define LGY 64
#define LGX 128

// ---- scratch layout inside the Z region of d_out ----
#define S_DEG   0
#define S_OFF   8192
#define S_CUR   16384
#define S_ESRC  24576
#define S_EW    286720
#define S_HCAT  1048576
#define S_H1    5242880
#define S_ZLH   7340032
#define S_KLP   9437184                // 256 floats
#define S_GLP   9437696                // 8192 floats

// loss kernel smem
#define LDK 136
#define LOSS_SMEM (192 * LDK * 2)
#define LDC 72

// WMMA hidden-GEMM smem layout (bf16 panels, ld = 72)
#define LDH 72
#define GW_SMEM  55296                  // Ah,Al(128xLDH) + Wh,Wl(64xLDH)
#define HD_SMEM  147456                 // + W4 panels + Cmu,Clv fp32

// ================= CSR build =================
__global__ void zero_deg_kernel(int* deg) {
    deg[blockIdx.x * 256 + threadIdx.x] = 0;
}
__global__ void hist_kernel(const int* __restrict__ ei, int* deg) {
    int e = blockIdx.x * 256 + threadIdx.x;
    atomicAdd(&deg[ei[EE + e]], 1);
}
__global__ void scan_kernel(const int* __restrict__ deg, int* off, int* cur) {
    __shared__ int s[256];
    int tid = threadIdx.x;
    int base = tid * 32;
    int loc[32];
    int sum = 0;
#pragma unroll
    for (int i = 0; i < 32; i++) { loc[i] = deg[base + i]; sum += loc[i]; }
    s[tid] = sum;
    __syncthreads();
    for (int o = 1; o < 256; o <<= 1) {
        int v = (tid >= o) ? s[tid - o] : 0;
        __syncthreads();
        s[tid] += v;
        __syncthreads();
    }
    int run = s[tid] - sum;
#pragma unroll
    for (int i = 0; i < 32; i++) {
        off[base + i] = run;
        cur[base + i] = run;
        run += loc[i];
    }
}
__global__ void fill_kernel(const int* __restrict__ ei, const float* __restrict__ w,
                            int* cur, int* esrc, float* ew) {
    int e = blockIdx.x * 256 + threadIdx.x;
    int src = ei[e];
    int dst = ei[EE + e];
    int slot = atomicAdd(&cur[dst], 1);
    esrc[slot] = src;
    ew[slot]   = w[e];
}

// ============ gather conv + fused combine ============
__global__ void gather_kernel(const float* __restrict__ x, float* __restrict__ hcat,
                              const int* __restrict__ deg, const int* __restrict__ off,
                              const int* __restrict__ esrc, const float* __restrict__ ew) {
    __shared__ int   ss[256];
    __shared__ float sw[256];
    int n = blockIdx.x, d = threadIdx.x;
    int beg = off[n];
    int dg  = deg[n];
    float acc = 0.f;
    for (int c = 0; c < dg; c += 256) {
        int m = min(256, dg - c);
        if (d < m) { ss[d] = esrc[beg + c + d]; sw[d] = ew[beg + c + d]; }
        __syncthreads();
#pragma unroll 4
        for (int j = 0; j < m; j++)
            acc = fmaf(x[(size_t)ss[j] * DD + d], sw[j], acc);
        __syncthreads();
    }
    hcat[n * 512 + d]       = x[(size_t)n * DD + d];
    hcat[n * 512 + 256 + d] = acc / fmaxf((float)dg, 1.f);
}

// ===== fp32 -> bf16 hi/lo split store =====
__device__ __forceinline__ void split4(__nv_bfloat16* H, __nv_bfloat16* L, int off, float4 v) {
    __nv_bfloat16 h0 = __float2bfloat16(v.x), h1 = __float2bfloat16(v.y);
    __nv_bfloat16 h2 = __float2bfloat16(v.z), h3 = __float2bfloat16(v.w);
    __nv_bfloat16 l0 = __float2bfloat16(v.x - __bfloat162float(h0));
    __nv_bfloat16 l1 = __float2bfloat16(v.y - __bfloat162float(h1));
    __nv_bfloat16 l2 = __float2bfloat16(v.z - __bfloat162float(h2));
    __nv_bfloat16 l3 = __float2bfloat16(v.w - __bfloat162float(h3));
    *(__nv_bfloat162*)(H + off)     = __nv_bfloat162(h0, h1);
    *(__nv_bfloat162*)(H + off + 2) = __nv_bfloat162(h2, h3);
    *(__nv_bfloat162*)(L + off)     = __nv_bfloat162(l0, l1);
    *(__nv_bfloat162*)(L + off + 2) = __nv_bfloat162(l2, l3);
}

// ====== WMMA hidden GEMM: C[8192,256] = act(A[.,KD] @ W + b) (+res), 3-pass split ======
template<bool RELU, bool RES, int KD>
__global__ void __launch_bounds__(256, 2) gemm_wmma(
    const float* __restrict__ A, const float* __restrict__ W,
    const float* __restrict__ bias, const float* __restrict__ res,
    float* __restrict__ C) {
    extern __shared__ __align__(16) char sm[];
    __nv_bfloat16* Ah = (__nv_bfloat16*)sm;        // 128 x LDH
    __nv_bfloat16* Al = Ah + 128 * LDH;
    __nv_bfloat16* Wh = Al + 128 * LDH;            // 64 x LDH
    __nv_bfloat16* Wl = Wh + 64 * LDH;
    int tid = threadIdx.x, wid = tid >> 5;
    int wm0 = (wid >> 1) * 32, wn0 = (wid & 1) * 32;
    int rowBase = blockIdx.y * 128, colBase = blockIdx.x * 64;

    wmma::fragment<wmma::accumulator, 16, 16, 16, float> acc[2][2];
#pragma unroll
    for (int m = 0; m < 2; m++)
#pragma unroll
        for (int n = 0; n < 2; n++) wmma::fill_fragment(acc[m][n], 0.f);

    for (int kc = 0; kc < KD / 64; kc++) {
        int kg = kc * 64;
        for (int idx = tid; idx < 128 * 16; idx += 256) {
            int r = idx >> 4, c4 = (idx & 15) << 2;
            float4 v = *(const float4*)(A + (size_t)(rowBase + r) * KD + kg + c4);
            split4(Ah, Al, r * LDH + c4, v);
        }
        for (int idx = tid; idx < 64 * 16; idx += 256) {
            int k = idx >> 4, c4 = (idx & 15) << 2;
            float4 v = *(const float4*)(W + (size_t)(kg + k) * 256 + colBase + c4);
            split4(Wh, Wl, k * LDH + c4, v);
        }
        __syncthreads();
#pragma unroll
        for (int ks = 0; ks < 4; ks++) {
            int k0 = ks * 16;
            wmma::fragment<wmma::matrix_a, 16, 16, 16, __nv_bfloat16, wmma::row_major> aH[2], aL[2];
            wmma::fragment<wmma::matrix_b, 16, 16, 16, __nv_bfloat16, wmma::row_major> bH[2], bL[2];
#pragma unroll
            for (int m = 0; m < 2; m++) {
                wmma::load_matrix_sync(aH[m], &Ah[(wm0 + m * 16) * LDH + k0], LDH);
                wmma::load_matrix_sync(aL[m], &Al[(wm0 + m * 16) * LDH + k0], LDH);
            }
#pragma unroll
            for (int n = 0; n < 2; n++) {
                wmma::load_matrix_sync(bH[n], &Wh[k0 * LDH + wn0 + n * 16], LDH);
                wmma::load_matrix_sync(bL[n], &Wl[k0 * LDH + wn0 + n * 16], LDH);
            }
#pragma unroll
            for (int m = 0; m < 2; m++)
#pragma unroll
                for (int n = 0; n < 2; n++) {
                    wmma::mma_sync(acc[m][n], aH[m], bH[n], acc[m][n]);
                    wmma::mma_sync(acc[m][n], aL[m], bH[n], acc[m][n]);
                    wmma::mma_sync(acc[m][n], aH[m], bL[n], acc[m][n]);
                }
        }
        __syncthreads();
    }

    float* Cs = (float*)sm;   // 128 x LDC fp32, reuses panels
#pragma unroll
    for (int m = 0; m < 2; m++)
#pragma unroll
        for (int n = 0; n < 2; n++)
            wmma::store_matrix_sync(&Cs[(wm0 + m * 16) * LDC + wn0 + n * 16],
                                    acc[m][n], LDC, wmma::mem_row_major);
    __syncthreads();

#pragma unroll
    for (int rb = 0; rb < 8; rb++) {
        int r = rb * 16 + (tid >> 4);
        int c = (tid & 15) << 2;
        float4 o = *(float4*)&Cs[r * LDC + c];
        float4 bv = *(const float4*)(bias + colBase + c);
        o.x += bv.x; o.y += bv.y; o.z += bv.z; o.w += bv.w;
        if (RELU) {
            o.x = fmaxf(o.x, 0.f); o.y = fmaxf(o.y, 0.f);
            o.z = fmaxf(o.z, 0.f); o.w = fmaxf(o.w, 0.f);
        }
        if (RES) {
            float4 rv = *(const float4*)(res + (size_t)(rowBase + r) * 256 + colBase + c);
            o.x += rv.x; o.y += rv.y; o.z += rv.z; o.w += rv.w;
        }
        *(float4*)(C + (size_t)(rowBase + r) * 256 + colBase + c) = o;
    }
}

// ====== WMMA heads: mu = enc2@W3+b3, lv = enc2@W4+b4 (both in one pass over A) ======
// MODE 0: Zl bf16 + KL partials.  MODE 1: Z fp32 (final).
template<int MODE>
__global__ void __launch_bounds__(256, 1) heads_wmma(
    const float* __restrict__ enc2,
    const float* __restrict__ W3, const float* __restrict__ b3,
    const float* __restrict__ W4, const float* __restrict__ b4,
    const float* __restrict__ eps,
    float* __restrict__ dstZ, __nv_bfloat16* __restrict__ zhi,
    float* __restrict__ klpart) {
    extern __shared__ __align__(16) char sm[];
    __nv_bfloat16* Ah  = (__nv_bfloat16*)sm;       // 128 x LDH
    __nv_bfloat16* Al  = Ah + 128 * LDH;
    __nv_bfloat16* W3h = Al + 128 * LDH;           // 64 x LDH each
    __nv_bfloat16* W3l = W3h + 64 * LDH;
    __nv_bfloat16* W4h = W3l + 64 * LDH;
    __nv_bfloat16* W4l = W4h + 64 * LDH;
    float* Cmu = (float*)(sm + 73728);             // 128 x LDC
    float* Clv = Cmu + 128 * LDC;
    int tid = threadIdx.x, wid = tid >> 5;
    int wm0 = (wid >> 1) * 32, wn0 = (wid & 1) * 32;
    int rowBase = blockIdx.y * 128, colBase = blockIdx.x * 64;

    wmma::fragment<wmma::accumulator, 16, 16, 16, float> ac3[2][2], ac4[2][2];
#pragma unroll
    for (int m = 0; m < 2; m++)
#pragma unroll
        for (int n = 0; n < 2; n++) {
            wmma::fill_fragment(ac3[m][n], 0.f);
            wmma::fill_fragment(ac4[m][n], 0.f);
        }

    for (int kc = 0; kc < 4; kc++) {
        int kg = kc * 64;
        for (int idx = tid; idx < 128 * 16; idx += 256) {
            int r = idx >> 4, c4 = (idx & 15) << 2;
            float4 v = *(const float4*)(enc2 + (size_t)(rowBase + r) * 256 + kg + c4);
            split4(Ah, Al, r * LDH + c4, v);
        }
        for (int idx = tid; idx < 64 * 16; idx += 256) {
            int k = idx >> 4, c4 = (idx & 15) << 2;
            float4 v3 = *(const float4*)(W3 + (size_t)(kg + k) * 256 + colBase + c4);
            split4(W3h, W3l, k * LDH + c4, v3);
            float4 v4 = *(const float4*)(W4 + (size_t)(kg + k) * 256 + colBase + c4);
            split4(W4h, W4l, k * LDH + c4, v4);
        }
        __syncthreads();
#pragma unroll
        for (int ks = 0; ks < 4; ks++) {
            int k0 = ks * 16;
            wmma::fragment<wmma::matrix_a, 16, 16, 16, __nv_bfloat16, wmma::row_major> aH[2], aL[2];
#pragma unroll
            for (int m = 0; m < 2; m++) {
                wmma::load_matrix_sync(aH[m], &Ah[(wm0 + m * 16) * LDH + k0], LDH);
                wmma::load_matrix_sync(aL[m], &Al[(wm0 + m * 16) * LDH + k0], LDH);
            }
            {
                wmma::fragment<wmma::matrix_b, 16, 16, 16, __nv_bfloat16, wmma::row_major> bH[2], bL[2];
#pragma unroll
                for (int n = 0; n < 2; n++) {
                    wmma::load_matrix_sync(bH[n], &W3h[k0 * LDH + wn0 + n * 16], LDH);
                    wmma::load_matrix_sync(bL[n], &W3l[k0 * LDH + wn0 + n * 16], LDH);
                }
#pragma unroll
                for (int m = 0; m < 2; m++)
#pragma unroll
                    for (int n = 0; n < 2; n++) {
                        wmma::mma_sync(ac3[m][n], aH[m], bH[n], ac3[m][n]);
                        wmma::mma_sync(ac3[m][n], aL[m], bH[n], ac3[m][n]);
                        wmma::mma_sync(ac3[m][n], aH[m], bL[n], ac3[m][n]);
                    }
            }
            {
                wmma::fragment<wmma::matrix_b, 16, 16, 16, __nv_bfloat16, wmma::row_major> bH[2], bL[2];
#pragma unroll
                for (int n = 0; n < 2; n++) {
                    wmma::load_matrix_sync(bH[n], &W4h[k0 * LDH + wn0 + n * 16], LDH);
                    wmma::load_matrix_sync(bL[n], &W4l[k0 * LDH + wn0 + n * 16], LDH);
                }
#pragma unroll
                for (int m = 0; m < 2; m++)
#pragma unroll
                    for (int n = 0; n < 2; n++) {
                        wmma::mma_sync(ac4[m][n], aH[m], bH[n], ac4[m][n]);
                        wmma::mma_sync(ac4[m][n], aL[m], bH[n], ac4[m][n]);
                        wmma::mma_sync(ac4[m][n], aH[m], bL[n], ac4[m][n]);
                    }
            }
        }
        __syncthreads();
    }

#pragma unroll
    for (int m = 0; m < 2; m++)
#pragma unroll
        for (int n = 0; n < 2; n++) {
            wmma::store_matrix_sync(&Cmu[(wm0 + m * 16) * LDC + wn0 + n * 16],
                                    ac3[m][n], LDC, wmma::mem_row_major);
            wmma::store_matrix_sync(&Clv[(wm0 + m * 16) * LDC + wn0 + n * 16],
                                    ac4[m][n], LDC, wmma::mem_row_major);
        }
    __syncthreads();

    float klsum = 0.f;
#pragma unroll
    for (int rb = 0; rb < 8; rb++) {
        int r = rb * 16 + (tid >> 4);
        int c = (tid & 15) << 2;
        int n = rowBase + r;
        int col = colBase + c;
        float4 mu4 = *(float4*)&Cmu[r * LDC + c];
        float4 lv4 = *(float4*)&Clv[r * LDC + c];
        float4 b3v = *(const float4*)(b3 + col);
        float4 b4v = *(const float4*)(b4 + col);
        float mu[4] = {mu4.x + b3v.x, mu4.y + b3v.y, mu4.z + b3v.z, mu4.w + b3v.w};
        float lv[4] = {lv4.x + b4v.x, lv4.y + b4v.y, lv4.z + b4v.z, lv4.w + b4v.w};
        float sg[4];
#pragma unroll
        for (int j = 0; j < 4; j++) sg[j] = __expf(0.5f * lv[j]);
        if (MODE == 0) {
            float4 es = make_float4(0.f, 0.f, 0.f, 0.f);
#pragma unroll
            for (int k = 0; k < KK; k++) {
                float4 e = *(const float4*)(eps + (size_t)(n * KK + k) * DD + col);
                es.x += e.x; es.y += e.y; es.z += e.z; es.w += e.w;
            }
            float zv[4];
            zv[0] = fmaf(sg[0], es.x * 0.125f, mu[0]);
            zv[1] = fmaf(sg[1], es.y * 0.125f, mu[1]);
            zv[2] = fmaf(sg[2], es.z * 0.125f, mu[2]);
            zv[3] = fmaf(sg[3], es.w * 0.125f, mu[3]);
            __nv_bfloat16 h0 = __float2bfloat16(zv[0]), h1 = __float2bfloat16(zv[1]);
            __nv_bfloat16 h2 = __float2bfloat16(zv[2]), h3 = __float2bfloat16(zv[3]);
            size_t base = (size_t)n * DD + col;
            *(__nv_bfloat162*)(zhi + base)     = __nv_bfloat162(h0, h1);
            *(__nv_bfloat162*)(zhi + base + 2) = __nv_bfloat162(h2, h3);
#pragma unroll
            for (int j = 0; j < 4; j++)
                klsum += 1.f + lv[j] - mu[j] * mu[j] - sg[j] * sg[j];
        } else {
#pragma unroll
            for (int k = 0; k < KK; k++) {
                float4 e = *(const float4*)(eps + (size_t)(n * KK + k) * DD + col);
                float4 o;
                o.x = fmaf(sg[0], e.x, mu[0]);
                o.y = fmaf(sg[1], e.y, mu[1]);
                o.z = fmaf(sg[2], e.z, mu[2]);
                o.w = fmaf(sg[3], e.w, mu[3]);
                *(float4*)(dstZ + (size_t)(n * KK + k) * DD + col) = o;
            }
        }
    }

    if (MODE == 0) {
        __shared__ float sred[256];
        sred[tid] = klsum; __syncthreads();
        for (int s = 128; s > 0; s >>= 1) {
            if (tid < s) sred[tid] += sred[tid + s];
            __syncthreads();
        }
        if (tid == 0) klpart[blockIdx.y * 4 + blockIdx.x] = sred[0];
    }
}

// ====== WMMA bf16 loss: single-pass Zl@Zl^T + BCE, M=128 x N=64 tiles ======
__global__ void __launch_bounds__(256, 2) loss_mma_kernel(
    const __nv_bfloat16* __restrict__ zhi,
    const float* __restrict__ ADJ, float* __restrict__ glpart) {
    int bi = blockIdx.y, bj = blockIdx.x;
    int tid = threadIdx.x;
    int rowBase = bi * 128, colBase = bj * 64;

    if (colBase + 64 <= rowBase) {
        if (tid == 0) glpart[bi * LGX + bj] = 0.f;
        return;
    }

    extern __shared__ __align__(16) char smc[];
    __nv_bfloat16* AH = (__nv_bfloat16*)smc;
    __nv_bfloat16* BH = AH + 128 * LDK;

    int wid = tid >> 5;
    int wm0 = (wid >> 1) * 32;
    int wn0 = (wid & 1) * 32;

    wmma::fragment<wmma::accumulator, 16, 16, 16, float> acc[2][2];
#pragma unroll
    for (int m = 0; m < 2; m++)
#pragma unroll
        for (int n = 0; n < 2; n++) wmma::fill_fragment(acc[m][n], 0.f);

    for (int kc = 0; kc < 2; kc++) {
        int kg = kc * 128;
        for (int idx = tid; idx < 128 * 16; idx += 256) {
            int r = idx >> 4, c8 = (idx & 15) << 3;
            *(uint4*)&AH[r * LDK + c8] =
                *(const uint4*)(zhi + (size_t)(rowBase + r) * 256 + kg + c8);
        }
        for (int idx = tid; idx < 64 * 16; idx += 256) {
            int r = idx >> 4, c8 = (idx & 15) << 3;
            *(uint4*)&BH[r * LDK + c8] =
                *(const uint4*)(zhi + (size_t)(colBase + r) * 256 + kg + c8);
        }
        __syncthreads();

#pragma unroll
        for (int ks = 0; ks < 8; ks++) {
            int k0 = ks * 16;
            wmma::fragment<wmma::matrix_a, 16, 16, 16, __nv_bfloat16, wmma::row_major> aH[2];
            wmma::fragment<wmma::matrix_b, 16, 16, 16, __nv_bfloat16, wmma::col_major> bH[2];
#pragma unroll
            for (int m = 0; m < 2; m++)
                wmma::load_matrix_sync(aH[m], &AH[(wm0 + m * 16) * LDK + k0], LDK);
#pragma unroll
            for (int n = 0; n < 2; n++)
                wmma::load_matrix_sync(bH[n], &BH[(wn0 + n * 16) * LDK + k0], LDK);
#pragma unroll
            for (int m = 0; m < 2; m++)
#pragma unroll
                for (int n = 0; n < 2; n++)
                    wmma::mma_sync(acc[m][n], aH[m], bH[n], acc[m][n]);
        }
        __syncthreads();
    }

    float* Cs = (float*)smc;
#pragma unroll
    for (int m = 0; m < 2; m++)
#pragma unroll
        for (int n = 0; n < 2; n++)
            wmma::store_matrix_sync(&Cs[(wm0 + m * 16) * LDC + wn0 + n * 16],
                                    acc[m][n], LDC, wmma::mem_row_major);
    __syncthreads();

    float term = 0.f;
    {
        int jl = tid & 63;
        int j = colBase + jl;
        for (int il = tid >> 6; il < 128; il += 4) {
            int i = rowBase + il;
            if (i > j) continue;
            float c = Cs[il * LDC + jl];
            float sp = fmaxf(c, 0.f) + __logf(1.f + __expf(-fabsf(c)));
            float a = ADJ[(size_t)i * NN + j];
            term += (i < j ? 2.f : 1.f) * sp - c * a;
        }
    }
    {
        int ilane = tid & 63;
        for (int jl = tid >> 6; jl < 64; jl += 4) {
            int j = colBase + jl;
#pragma unroll
            for (int ib = 0; ib < 128; ib += 64) {
                int il = ib + ilane;
                int i = rowBase + il;
                if (i < j)
                    term -= Cs[il * LDC + jl] * ADJ[(size_t)j * NN + i];
            }
        }
    }

    __shared__ float sred[256];
    sred[tid] = term; __syncthreads();
    for (int s = 128; s > 0; s >>= 1) {
        if (tid < s) sred[tid] += sred[tid + s];
        __syncthreads();
    }
    if (tid == 0) glpart[bi * LGX + bj] = sred[0];
}

// ================= final reduction =================
__global__ void finalize_kernel(const float* __restrict__ klpart,
                                const float* __restrict__ glpart,
                                float* __restrict__ outScalar) {
    __shared__ double sk[256], sg[256];
    int t = threadIdx.x;
    double a = 0.0, b = 0.0;
    a += (double)klpart[t];            // exactly 256 KL partials
    for (int i = t; i < LGY * LGX; i += 256)  b += (double)glpart[i];
    sk[t] = a; sg[t] = b; __syncthreads();
    for (int s = 128; s > 0; s >>= 1) {
        if (t < s) { sk[t] += sk[t + s]; sg[t] += sg[t + s]; }
        __syncthreads();
    }
    if (t == 0) {
        double kl = -0.5 * sk[0] / (double)NN;
        double gl = sg[0] / ((double)NN * (double)NN);
        *outScalar = (float)(kl + gl);
    }
}

// ================= host launcher =================
extern "C" void kernel_launch(void* const* d_in, const int* in_sizes, int n_in,
                              void* d_out, int out_size) {
    const float* enc = (const float*)d_in[0];
    const int*   ei  = (const int*)d_in[1];
    const float* w   = (const float*)d_in[2];
    const float* ADJ = (const float*)d_in[3];
    const float* eps = (const float*)d_in[4];
    const float* W1 = (const float*)d_in[5];  const float* b1 = (const float*)d_in[6];
    const float* W2 = (const float*)d_in[7];  const float* b2 = (const float*)d_in[8];
    const float* W3 = (const float*)d_in[9];  const float* b3 = (const float*)d_in[10];
    const float* W4 = (const float*)d_in[11]; const float* b4 = (const float*)d_in[12];

    float* out  = (float*)d_out;
    float* enc2 = out;
    float* zreg = out + (size_t)NN * DD;

    int*   deg  = (int*)  (zreg + S_DEG);
    int*   off  = (int*)  (zreg + S_OFF);
    int*   cur  = (int*)  (zreg + S_CUR);
    int*   esrc = (int*)  (zreg + S_ESRC);
    float* ew   =          zreg + S_EW;
    float* hcat =          zreg + S_HCAT;
    float* h1   =          zreg + S_H1;
    __nv_bfloat16* zhi = (__nv_bfloat16*)(zreg + S_ZLH);
    float* klp  =          zreg + S_KLP;
    float* glp  =          zreg + S_GLP;
    float* outScalar = out + (size_t)out_size - 1;

    cudaFuncSetAttribute(loss_mma_kernel,
                         cudaFuncAttributeMaxDynamicSharedMemorySize, LOSS_SMEM);
    cudaFuncSetAttribute(gemm_wmma<true, false, 512>,
                         cudaFuncAttributeMaxDynamicSharedMemorySize, GW_SMEM);
    cudaFuncSetAttribute(gemm_wmma<true, true, 512>,
                         cudaFuncAttributeMaxDynamicSharedMemorySize, GW_SMEM);
    cudaFuncSetAttribute(heads_wmma<0>,
                         cudaFuncAttributeMaxDynamicSharedMemorySize, HD_SMEM);
    cudaFuncSetAttribute(heads_wmma<1>,
                         cudaFuncAttributeMaxDynamicSharedMemorySize, HD_SMEM);

    // CSR build
    zero_deg_kernel<<<NN / 256, 256>>>(deg);
    hist_kernel<<<EE / 256, 256>>>(ei, deg);
    scan_kernel<<<1, 256>>>(deg, off, cur);
    fill_kernel<<<EE / 256, 256>>>(ei, w, cur, esrc, ew);

    // conv1 + linear1 + relu
    gather_kernel<<<NN, 256>>>(enc, hcat, deg, off, esrc, ew);
    gemm_wmma<true, false, 512><<<dim3(4, 64), 256, GW_SMEM>>>(hcat, W1, b1, nullptr, h1);

    // conv2 + linear2 + relu + residual -> enc2
    gather_kernel<<<NN, 256>>>(h1, hcat, deg, off, esrc, ew);
    gemm_wmma<true, true, 512><<<dim3(4, 64), 256, GW_SMEM>>>(hcat, W2, b2, enc, enc2);

    // fused heads -> Zl bf16 + KL partials
    heads_wmma<0><<<dim3(4, 64), 256, HD_SMEM>>>(enc2, W3, b3, W4, b4, eps,
                                                 nullptr, zhi, klp);

    // WMMA loss GEMM + BCE
    loss_mma_kernel<<<dim3(LGX, LGY), 256, LOSS_SMEM>>>(zhi, ADJ, glp);

    // loss scalar before Z overwrites partials
    finalize_kernel<<<1, 256>>>(klp, glp, outScalar);

    // final: write Z over the scratch arena
    heads_wmma<1><<<dim3(4, 64), 256, HD_SMEM>>>(enc2, W3, b3, W4, b4, eps,
                                                 zreg, nullptr, nullptr);
}

// round 11
// speedup vs baseline: 1.5103x; 1.1303x over previous
#include <cuda_runtime.h>
#include <cuda_bf16.h>
#include <mma.h>
#include <math.h>
#include <stdint.h>

using namespace nvcuda;

#define NN 8192
#define DD 256
#define EE 262144
#define KK 8

// ---- arena layout inside Z region of d_out (16,777,216 floats) ----
#define S_DEG   0
#define S_OFF   8192
#define S_CUR   16384
#define S_ESRC  24576
#define S_EW    286720
#define S_WSP   548864                 // pre-split weights (bf16 area, 393,216 floats)
#define S_HCH   1048576                // hcat_hi bf16 [8192,512] (2,097,152 floats)
#define S_HCL   3145728                // hcat_lo
#define S_H1    5242880                // h1 fp32 [8192,256]
#define S_E2H   7340032                // enc2_hi bf16 (1,048,576 floats)
#define S_E2L   8388608                // enc2_lo
#define S_ZLH   9437184                // Zl_hi bf16
#define S_KLP   10485760               // 256 floats
#define S_GLP   10486016               // 4096 floats

// pre-split weight offsets (bf16 units within wsp)
#define W1H 0
#define W1L 131072
#define W2H 262144
#define W2L 393216
#define W3H 524288
#define W3L 589824
#define W4H 655360
#define W4L 720896

// tiles / smem
#define LDA 136                        // A panel ld (K chunk 128 + pad)
#define LDW 72                         // W panel ld (64 n + pad)
#define LDC 72
#define GW_SMEM  106496                // Ah,Al(128x136) + Wh,Wl(128x72)
#define HD_SMEM  143360                // Ah,Al + 4 W panels
#define LDC2 132
#define LOSS_SMEM 69632                // AH,BH 128x136 bf16 each

// ================= CSR build =================
__global__ void zero_deg_kernel(int* deg) {
    deg[blockIdx.x * 256 + threadIdx.x] = 0;
}
__global__ void hist_kernel(const int* __restrict__ ei, int* deg) {
    int e = blockIdx.x * 256 + threadIdx.x;
    atomicAdd(&deg[ei[EE + e]], 1);
}
__global__ void scan_kernel(const int* __restrict__ deg, int* off, int* cur) {
    __shared__ int s[256];
    int tid = threadIdx.x;
    int base = tid * 32;
    int loc[32];
    int sum = 0;
#pragma unroll
    for (int i = 0; i < 32; i++) { loc[i] = deg[base + i]; sum += loc[i]; }
    s[tid] = sum;
    __syncthreads();
    for (int o = 1; o < 256; o <<= 1) {
        int v = (tid >= o) ? s[tid - o] : 0;
        __syncthreads();
        s[tid] += v;
        __syncthreads();
    }
    int run = s[tid] - sum;
#pragma unroll
    for (int i = 0; i < 32; i++) {
        off[base + i] = run;
        cur[base + i] = run;
        run += loc[i];
    }
}
__global__ void fill_kernel(const int* __restrict__ ei, const float* __restrict__ w,
                            int* cur, int* esrc, float* ew) {
    int e = blockIdx.x * 256 + threadIdx.x;
    int src = ei[e];
    int dst = ei[EE + e];
    int slot = atomicAdd(&cur[dst], 1);
    esrc[slot] = src;
    ew[slot]   = w[e];
}

// ================= one-shot fp32 -> bf16 hi/lo weight split =================
__global__ void split_w_kernel(const float* __restrict__ src,
                               __nv_bfloat16* __restrict__ h,
                               __nv_bfloat16* __restrict__ l, int n) {
    int i = (blockIdx.x * 256 + threadIdx.x) * 4;
    if (i >= n) return;
    float4 v = *(const float4*)(src + i);
    __nv_bfloat16 h0 = __float2bfloat16(v.x), h1 = __float2bfloat16(v.y);
    __nv_bfloat16 h2 = __float2bfloat16(v.z), h3 = __float2bfloat16(v.w);
    *(__nv_bfloat162*)(h + i)     = __nv_bfloat162(h0, h1);
    *(__nv_bfloat162*)(h + i + 2) = __nv_bfloat162(h2, h3);
    *(__nv_bfloat162*)(l + i) = __nv_bfloat162(
        __float2bfloat16(v.x - __bfloat162float(h0)),
        __float2bfloat16(v.y - __bfloat162float(h1)));
    *(__nv_bfloat162*)(l + i + 2) = __nv_bfloat162(
        __float2bfloat16(v.z - __bfloat162float(h2)),
        __float2bfloat16(v.w - __bfloat162float(h3)));
}

// ============ gather conv + combine, emitting split bf16 hcat ============
__global__ void gather_kernel(const float* __restrict__ x,
                              __nv_bfloat16* __restrict__ hch,
                              __nv_bfloat16* __restrict__ hcl,
                              const int* __restrict__ deg, const int* __restrict__ off,
                              const int* __restrict__ esrc, const float* __restrict__ ew) {
    __shared__ int   ss[256];
    __shared__ float sw[256];
    int n = blockIdx.x, d = threadIdx.x;
    int beg = off[n];
    int dg  = deg[n];
    float acc = 0.f;
    for (int c = 0; c < dg; c += 256) {
        int m = min(256, dg - c);
        if (d < m) { ss[d] = esrc[beg + c + d]; sw[d] = ew[beg + c + d]; }
        __syncthreads();
#pragma unroll 4
        for (int j = 0; j < m; j++)
            acc = fmaf(x[(size_t)ss[j] * DD + d], sw[j], acc);
        __syncthreads();
    }
    float xv = x[(size_t)n * DD + d];
    float av = acc / fmaxf((float)dg, 1.f);
    __nv_bfloat16 xh = __float2bfloat16(xv);
    __nv_bfloat16 ah = __float2bfloat16(av);
    int base = n * 512 + d;
    hch[base]       = xh;
    hch[base + 256] = ah;
    hcl[base]       = __float2bfloat16(xv - __bfloat162float(xh));
    hcl[base + 256] = __float2bfloat16(av - __bfloat162float(ah));
}

// ====== bf16 GEMM (pre-split inputs): C = act(A@W + b) (+res) (+split-out) ======
template<bool RELU, bool RES, bool SPLITOUT, int KD>
__global__ void __launch_bounds__(256, 2) gemm_bf16(
    const __nv_bfloat16* __restrict__ Ahg, const __nv_bfloat16* __restrict__ Alg,
    const __nv_bfloat16* __restrict__ Whg, const __nv_bfloat16* __restrict__ Wlg,
    const float* __restrict__ bias, const float* __restrict__ res,
    float* __restrict__ C, __nv_bfloat16* __restrict__ Ch, __nv_bfloat16* __restrict__ Cl) {
    extern __shared__ __align__(16) char sm[];
    __nv_bfloat16* Ah = (__nv_bfloat16*)sm;        // 128 x LDA
    __nv_bfloat16* Al = Ah + 128 * LDA;
    __nv_bfloat16* Wh = Al + 128 * LDA;            // 128 x LDW (k x n)
    __nv_bfloat16* Wl = Wh + 128 * LDW;
    int tid = threadIdx.x, wid = tid >> 5;
    int wm0 = (wid >> 1) * 32, wn0 = (wid & 1) * 32;
    int rowBase = blockIdx.y * 128, colBase = blockIdx.x * 64;

    wmma::fragment<wmma::accumulator, 16, 16, 16, float> acc[2][2];
#pragma unroll
    for (int m = 0; m < 2; m++)
#pragma unroll
        for (int n = 0; n < 2; n++) wmma::fill_fragment(acc[m][n], 0.f);

    for (int kc = 0; kc < KD / 128; kc++) {
        int kg = kc * 128;
        for (int idx = tid; idx < 128 * 16; idx += 256) {
            int r = idx >> 4, c8 = (idx & 15) << 3;
            size_t g = (size_t)(rowBase + r) * KD + kg + c8;
            *(uint4*)&Ah[r * LDA + c8] = *(const uint4*)(Ahg + g);
            *(uint4*)&Al[r * LDA + c8] = *(const uint4*)(Alg + g);
        }
        for (int idx = tid; idx < 128 * 8; idx += 256) {
            int k = idx >> 3, c8 = (idx & 7) << 3;
            size_t g = (size_t)(kg + k) * 256 + colBase + c8;
            *(uint4*)&Wh[k * LDW + c8] = *(const uint4*)(Whg + g);
            *(uint4*)&Wl[k * LDW + c8] = *(const uint4*)(Wlg + g);
        }
        __syncthreads();
#pragma unroll
        for (int ks = 0; ks < 8; ks++) {
            int k0 = ks * 16;
            wmma::fragment<wmma::matrix_a, 16, 16, 16, __nv_bfloat16, wmma::row_major> aH[2], aL[2];
            wmma::fragment<wmma::matrix_b, 16, 16, 16, __nv_bfloat16, wmma::row_major> bH[2], bL[2];
#pragma unroll
            for (int m = 0; m < 2; m++) {
                wmma::load_matrix_sync(aH[m], &Ah[(wm0 + m * 16) * LDA + k0], LDA);
                wmma::load_matrix_sync(aL[m], &Al[(wm0 + m * 16) * LDA + k0], LDA);
            }
#pragma unroll
            for (int n = 0; n < 2; n++) {
                wmma::load_matrix_sync(bH[n], &Wh[k0 * LDW + wn0 + n * 16], LDW);
                wmma::load_matrix_sync(bL[n], &Wl[k0 * LDW + wn0 + n * 16], LDW);
            }
#pragma unroll
            for (int m = 0; m < 2; m++)
#pragma unroll
                for (int n = 0; n < 2; n++) {
                    wmma::mma_sync(acc[m][n], aH[m], bH[n], acc[m][n]);
                    wmma::mma_sync(acc[m][n], aL[m], bH[n], acc[m][n]);
                    wmma::mma_sync(acc[m][n], aH[m], bL[n], acc[m][n]);
                }
        }
        __syncthreads();
    }

    float* Cs = (float*)sm;   // 128 x LDC fp32
#pragma unroll
    for (int m = 0; m < 2; m++)
#pragma unroll
        for (int n = 0; n < 2; n++)
            wmma::store_matrix_sync(&Cs[(wm0 + m * 16) * LDC + wn0 + n * 16],
                                    acc[m][n], LDC, wmma::mem_row_major);
    __syncthreads();

#pragma unroll
    for (int rb = 0; rb < 8; rb++) {
        int r = rb * 16 + (tid >> 4);
        int c = (tid & 15) << 2;
        float4 o = *(float4*)&Cs[r * LDC + c];
        float4 bv = *(const float4*)(bias + colBase + c);
        o.x += bv.x; o.y += bv.y; o.z += bv.z; o.w += bv.w;
        if (RELU) {
            o.x = fmaxf(o.x, 0.f); o.y = fmaxf(o.y, 0.f);
            o.z = fmaxf(o.z, 0.f); o.w = fmaxf(o.w, 0.f);
        }
        if (RES) {
            float4 rv = *(const float4*)(res + (size_t)(rowBase + r) * 256 + colBase + c);
            o.x += rv.x; o.y += rv.y; o.z += rv.z; o.w += rv.w;
        }
        size_t gidx = (size_t)(rowBase + r) * 256 + colBase + c;
        *(float4*)(C + gidx) = o;
        if (SPLITOUT) {
            __nv_bfloat16 h0 = __float2bfloat16(o.x), h1 = __float2bfloat16(o.y);
            __nv_bfloat16 h2 = __float2bfloat16(o.z), h3 = __float2bfloat16(o.w);
            *(__nv_bfloat162*)(Ch + gidx)     = __nv_bfloat162(h0, h1);
            *(__nv_bfloat162*)(Ch + gidx + 2) = __nv_bfloat162(h2, h3);
            *(__nv_bfloat162*)(Cl + gidx) = __nv_bfloat162(
                __float2bfloat16(o.x - __bfloat162float(h0)),
                __float2bfloat16(o.y - __bfloat162float(h1)));
            *(__nv_bfloat162*)(Cl + gidx + 2) = __nv_bfloat162(
                __float2bfloat16(o.z - __bfloat162float(h2)),
                __float2bfloat16(o.w - __bfloat162float(h3)));
        }
    }
}

// helper: fp32 -> bf16 hi/lo into smem at 4-elem granularity
__device__ __forceinline__ void split4s(__nv_bfloat16* H, __nv_bfloat16* L, int off, float4 v) {
    __nv_bfloat16 h0 = __float2bfloat16(v.x), h1 = __float2bfloat16(v.y);
    __nv_bfloat16 h2 = __float2bfloat16(v.z), h3 = __float2bfloat16(v.w);
    *(__nv_bfloat162*)(H + off)     = __nv_bfloat162(h0, h1);
    *(__nv_bfloat162*)(H + off + 2) = __nv_bfloat162(h2, h3);
    *(__nv_bfloat162*)(L + off) = __nv_bfloat162(
        __float2bfloat16(v.x - __bfloat162float(h0)),
        __float2bfloat16(v.y - __bfloat162float(h1)));
    *(__nv_bfloat162*)(L + off + 2) = __nv_bfloat162(
        __float2bfloat16(v.z - __bfloat162float(h2)),
        __float2bfloat16(v.w - __bfloat162float(h3)));
}

// ====== heads: mu/lv via dual GEMM. MODE0: pre-split inputs -> Zl + KL.
//        MODE1: fp32 inputs (self-split; arena-safe) -> Z (final).
template<int MODE>
__global__ void __launch_bounds__(256, 1) heads_wmma(
    const float* __restrict__ enc2f,
    const __nv_bfloat16* __restrict__ e2h, const __nv_bfloat16* __restrict__ e2l,
    const float* __restrict__ W3f, const float* __restrict__ W4f,
    const __nv_bfloat16* __restrict__ W3h, const __nv_bfloat16* __restrict__ W3l,
    const __nv_bfloat16* __restrict__ W4h, const __nv_bfloat16* __restrict__ W4l,
    const float* __restrict__ b3, const float* __restrict__ b4,
    const float* __restrict__ eps,
    float* __restrict__ dstZ, __nv_bfloat16* __restrict__ zhi,
    float* __restrict__ klpart) {
    extern __shared__ __align__(16) char sm[];
    __nv_bfloat16* Ah  = (__nv_bfloat16*)sm;       // 128 x LDA
    __nv_bfloat16* Al  = Ah + 128 * LDA;
    __nv_bfloat16* P3h = Al + 128 * LDA;           // 128 x LDW each
    __nv_bfloat16* P3l = P3h + 128 * LDW;
    __nv_bfloat16* P4h = P3l + 128 * LDW;
    __nv_bfloat16* P4l = P4h + 128 * LDW;
    int tid = threadIdx.x, wid = tid >> 5;
    int wm0 = (wid >> 1) * 32, wn0 = (wid & 1) * 32;
    int rowBase = blockIdx.y * 128, colBase = blockIdx.x * 64;

    wmma::fragment<wmma::accumulator, 16, 16, 16, float> ac3[2][2], ac4[2][2];
#pragma unroll
    for (int m = 0; m < 2; m++)
#pragma unroll
        for (int n = 0; n < 2; n++) {
            wmma::fill_fragment(ac3[m][n], 0.f);
            wmma::fill_fragment(ac4[m][n], 0.f);
        }

    for (int kc = 0; kc < 2; kc++) {
        int kg = kc * 128;
        if (MODE == 0) {
            for (int idx = tid; idx < 128 * 16; idx += 256) {
                int r = idx >> 4, c8 = (idx & 15) << 3;
                size_t g = (size_t)(rowBase + r) * 256 + kg + c8;
                *(uint4*)&Ah[r * LDA + c8] = *(const uint4*)(e2h + g);
                *(uint4*)&Al[r * LDA + c8] = *(const uint4*)(e2l + g);
            }
            for (int idx = tid; idx < 128 * 8; idx += 256) {
                int k = idx >> 3, c8 = (idx & 7) << 3;
                size_t g = (size_t)(kg + k) * 256 + colBase + c8;
                *(uint4*)&P3h[k * LDW + c8] = *(const uint4*)(W3h + g);
                *(uint4*)&P3l[k * LDW + c8] = *(const uint4*)(W3l + g);
                *(uint4*)&P4h[k * LDW + c8] = *(const uint4*)(W4h + g);
                *(uint4*)&P4l[k * LDW + c8] = *(const uint4*)(W4l + g);
            }
        } else {
            for (int idx = tid; idx < 128 * 32; idx += 256) {
                int r = idx >> 5, c4 = (idx & 31) << 2;
                float4 v = *(const float4*)(enc2f + (size_t)(rowBase + r) * 256 + kg + c4);
                split4s(Ah, Al, r * LDA + c4, v);
            }
            for (int idx = tid; idx < 128 * 16; idx += 256) {
                int k = idx >> 4, c4 = (idx & 15) << 2;
                size_t g = (size_t)(kg + k) * 256 + colBase + c4;
                split4s(P3h, P3l, k * LDW + c4, *(const float4*)(W3f + g));
                split4s(P4h, P4l, k * LDW + c4, *(const float4*)(W4f + g));
            }
        }
        __syncthreads();
#pragma unroll
        for (int ks = 0; ks < 8; ks++) {
            int k0 = ks * 16;
            wmma::fragment<wmma::matrix_a, 16, 16, 16, __nv_bfloat16, wmma::row_major> aH[2], aL[2];
#pragma unroll
            for (int m = 0; m < 2; m++) {
                wmma::load_matrix_sync(aH[m], &Ah[(wm0 + m * 16) * LDA + k0], LDA);
                wmma::load_matrix_sync(aL[m], &Al[(wm0 + m * 16) * LDA + k0], LDA);
            }
            {
                wmma::fragment<wmma::matrix_b, 16, 16, 16, __nv_bfloat16, wmma::row_major> bH[2], bL[2];
#pragma unroll
                for (int n = 0; n < 2; n++) {
                    wmma::load_matrix_sync(bH[n], &P3h[k0 * LDW + wn0 + n * 16], LDW);
                    wmma::load_matrix_sync(bL[n], &P3l[k0 * LDW + wn0 + n * 16], LDW);
                }
#pragma unroll
                for (int m = 0; m < 2; m++)
#pragma unroll
                    for (int n = 0; n < 2; n++) {
                        wmma::mma_sync(ac3[m][n], aH[m], bH[n], ac3[m][n]);
                        wmma::mma_sync(ac3[m][n], aL[m], bH[n], ac3[m][n]);
                        wmma::mma_sync(ac3[m][n], aH[m], bL[n], ac3[m][n]);
                    }
            }
            {
                wmma::fragment<wmma::matrix_b, 16, 16, 16, __nv_bfloat16, wmma::row_major> bH[2], bL[2];
#pragma unroll
                for (int n = 0; n < 2; n++) {
                    wmma::load_matrix_sync(bH[n], &P4h[k0 * LDW + wn0 + n * 16], LDW);
                    wmma::load_matrix_sync(bL[n], &P4l[k0 * LDW + wn0 + n * 16], LDW);
                }
#pragma unroll
                for (int m = 0; m < 2; m++)
#pragma unroll
                    for (int n = 0; n < 2; n++) {
                        wmma::mma_sync(ac4[m][n], aH[m], bH[n], ac4[m][n]);
                        wmma::mma_sync(ac4[m][n], aL[m], bH[n], ac4[m][n]);
                        wmma::mma_sync(ac4[m][n], aH[m], bL[n], ac4[m][n]);
                    }
            }
        }
        __syncthreads();
    }

    float* Cmu = (float*)sm;                 // 128 x LDC
    float* Clv = Cmu + 128 * LDC;
#pragma unroll
    for (int m = 0; m < 2; m++)
#pragma unroll
        for (int n = 0; n < 2; n++) {
            wmma::store_matrix_sync(&Cmu[(wm0 + m * 16) * LDC + wn0 + n * 16],
                                    ac3[m][n], LDC, wmma::mem_row_major);
            wmma::store_matrix_sync(&Clv[(wm0 + m * 16) * LDC + wn0 + n * 16],
                                    ac4[m][n], LDC, wmma::mem_row_major);
        }
    __syncthreads();

    float klsum = 0.f;
#pragma unroll
    for (int rb = 0; rb < 8; rb++) {
        int r = rb * 16 + (tid >> 4);
        int c = (tid & 15) << 2;
        int n = rowBase + r;
        int col = colBase + c;
        float4 mu4 = *(float4*)&Cmu[r * LDC + c];
        float4 lv4 = *(float4*)&Clv[r * LDC + c];
        float4 b3v = *(const float4*)(b3 + col);
        float4 b4v = *(const float4*)(b4 + col);
        float mu[4] = {mu4.x + b3v.x, mu4.y + b3v.y, mu4.z + b3v.z, mu4.w + b3v.w};
        float lv[4] = {lv4.x + b4v.x, lv4.y + b4v.y, lv4.z + b4v.z, lv4.w + b4v.w};
        float sg[4];
#pragma unroll
        for (int j = 0; j < 4; j++) sg[j] = __expf(0.5f * lv[j]);
        if (MODE == 0) {
            float4 es = make_float4(0.f, 0.f, 0.f, 0.f);
#pragma unroll
            for (int k = 0; k < KK; k++) {
                float4 e = *(const float4*)(eps + (size_t)(n * KK + k) * DD + col);
                es.x += e.x; es.y += e.y; es.z += e.z; es.w += e.w;
            }
            float zv[4];
            zv[0] = fmaf(sg[0], es.x * 0.125f, mu[0]);
            zv[1] = fmaf(sg[1], es.y * 0.125f, mu[1]);
            zv[2] = fmaf(sg[2], es.z * 0.125f, mu[2]);
            zv[3] = fmaf(sg[3], es.w * 0.125f, mu[3]);
            size_t base = (size_t)n * DD + col;
            *(__nv_bfloat162*)(zhi + base) =
                __nv_bfloat162(__float2bfloat16(zv[0]), __float2bfloat16(zv[1]));
            *(__nv_bfloat162*)(zhi + base + 2) =
                __nv_bfloat162(__float2bfloat16(zv[2]), __float2bfloat16(zv[3]));
#pragma unroll
            for (int j = 0; j < 4; j++)
                klsum += 1.f + lv[j] - mu[j] * mu[j] - sg[j] * sg[j];
        } else {
#pragma unroll
            for (int k = 0; k < KK; k++) {
                float4 e = *(const float4*)(eps + (size_t)(n * KK + k) * DD + col);
                float4 o;
                o.x = fmaf(sg[0], e.x, mu[0]);
                o.y = fmaf(sg[1], e.y, mu[1]);
                o.z = fmaf(sg[2], e.z, mu[2]);
                o.w = fmaf(sg[3], e.w, mu[3]);
                *(float4*)(dstZ + (size_t)(n * KK + k) * DD + col) = o;
            }
        }
    }

    if (MODE == 0) {
        __shared__ float sred[256];
        sred[tid] = klsum; __syncthreads();
        for (int s = 128; s > 0; s >>= 1) {
            if (tid < s) sred[tid] += sred[tid + s];
            __syncthreads();
        }
        if (tid == 0) klpart[blockIdx.y * 4 + blockIdx.x] = sred[0];
    }
}

// ====== WMMA bf16 loss: Zl@Zl^T + BCE, 128x128 tiles ======
__global__ void __launch_bounds__(256, 2) loss_mma_kernel(
    const __nv_bfloat16* __restrict__ zhi,
    const float* __restrict__ ADJ, float* __restrict__ glpart) {
    int bi = blockIdx.y, bj = blockIdx.x;
    int tid = threadIdx.x;
    if (bj < bi) {
        if (tid == 0) glpart[bi * 64 + bj] = 0.f;
        return;
    }
    int rowBase = bi * 128, colBase = bj * 128;

    extern __shared__ __align__(16) char smc[];
    __nv_bfloat16* AH = (__nv_bfloat16*)smc;        // 128 x LDA
    __nv_bfloat16* BH = AH + 128 * LDA;

    int wid = tid >> 5;
    int wm0 = (wid >> 1) * 32;      // 4 row groups
    int wn0 = (wid & 1) * 64;       // 2 col groups of 64

    wmma::fragment<wmma::accumulator, 16, 16, 16, float> acc[2][4];
#pragma unroll
    for (int m = 0; m < 2; m++)
#pragma unroll
        for (int n = 0; n < 4; n++) wmma::fill_fragment(acc[m][n], 0.f);

    for (int kc = 0; kc < 2; kc++) {
        int kg = kc * 128;
        for (int idx = tid; idx < 128 * 16; idx += 256) {
            int r = idx >> 4, c8 = (idx & 15) << 3;
            *(uint4*)&AH[r * LDA + c8] =
                *(const uint4*)(zhi + (size_t)(rowBase + r) * 256 + kg + c8);
            *(uint4*)&BH[r * LDA + c8] =
                *(const uint4*)(zhi + (size_t)(colBase + r) * 256 + kg + c8);
        }
        __syncthreads();
#pragma unroll
        for (int ks = 0; ks < 8; ks++) {
            int k0 = ks * 16;
            wmma::fragment<wmma::matrix_a, 16, 16, 16, __nv_bfloat16, wmma::row_major> aH[2];
#pragma unroll
            for (int m = 0; m < 2; m++)
                wmma::load_matrix_sync(aH[m], &AH[(wm0 + m * 16) * LDA + k0], LDA);
#pragma unroll
            for (int n = 0; n < 4; n++) {
                wmma::fragment<wmma::matrix_b, 16, 16, 16, __nv_bfloat16, wmma::col_major> bH;
                wmma::load_matrix_sync(bH, &BH[(wn0 + n * 16) * LDA + k0], LDA);
#pragma unroll
                for (int m = 0; m < 2; m++)
                    wmma::mma_sync(acc[m][n], aH[m], bH, acc[m][n]);
            }
        }
        __syncthreads();
    }

    float* Cs = (float*)smc;   // 128 x LDC2 fp32 = 67,584 B
#pragma unroll
    for (int m = 0; m < 2; m++)
#pragma unroll
        for (int n = 0; n < 4; n++)
            wmma::store_matrix_sync(&Cs[(wm0 + m * 16) * LDC2 + wn0 + n * 16],
                                    acc[m][n], LDC2, wmma::mem_row_major);
    __syncthreads();

    float term = 0.f;
    {
        int jl = tid & 127;
        int j = colBase + jl;
        for (int il = tid >> 7; il < 128; il += 2) {
            int i = rowBase + il;
            if (i > j) continue;
            float c = Cs[il * LDC2 + jl];
            float sp = fmaxf(c, 0.f) + __logf(1.f + __expf(-fabsf(c)));
            float a = ADJ[(size_t)i * NN + j];
            term += (i < j ? 2.f : 1.f) * sp - c * a;
        }
    }
    {
        int il = tid & 127;
        int i = rowBase + il;
        for (int jl = tid >> 7; jl < 128; jl += 2) {
            int j = colBase + jl;
            if (i < j)
                term -= Cs[il * LDC2 + jl] * ADJ[(size_t)j * NN + i];
        }
    }

    __shared__ float sred[256];
    sred[tid] = term; __syncthreads();
    for (int s = 128; s > 0; s >>= 1) {
        if (tid < s) sred[tid] += sred[tid + s];
        __syncthreads();
    }
    if (tid == 0) glpart[bi * 64 + bj] = sred[0];
}

// ================= final reduction =================
__global__ void finalize_kernel(const float* __restrict__ klpart,
                                const float* __restrict__ glpart,
                                float* __restrict__ outScalar) {
    __shared__ double sk[256], sg[256];
    int t = threadIdx.x;
    double a = (double)klpart[t];
    double b = 0.0;
    for (int i = t; i < 4096; i += 256) b += (double)glpart[i];
    sk[t] = a; sg[t] = b; __syncthreads();
    for (int s = 128; s > 0; s >>= 1) {
        if (t < s) { sk[t] += sk[t + s]; sg[t] += sg[t + s]; }
        __syncthreads();
    }
    if (t == 0) {
        double kl = -0.5 * sk[0] / (double)NN;
        double gl = sg[0] / ((double)NN * (double)NN);
        *outScalar = (float)(kl + gl);
    }
}

// ================= host launcher =================
extern "C" void kernel_launch(void* const* d_in, const int* in_sizes, int n_in,
                              void* d_out, int out_size) {
    const float* enc = (const float*)d_in[0];
    const int*   ei  = (const int*)d_in[1];
    const float* w   = (const float*)d_in[2];
    const float* ADJ = (const float*)d_in[3];
    const float* eps = (const float*)d_in[4];
    const float* W1 = (const float*)d_in[5];  const float* b1 = (const float*)d_in[6];
    const float* W2 = (const float*)d_in[7];  const float* b2 = (const float*)d_in[8];
    const float* W3 = (const float*)d_in[9];  const float* b3 = (const float*)d_in[10];
    const float* W4 = (const float*)d_in[11]; const float* b4 = (const float*)d_in[12];

    float* out  = (float*)d_out;
    float* enc2 = out;
    float* zreg = out + (size_t)NN * DD;

    int*   deg  = (int*)  (zreg + S_DEG);
    int*   off  = (int*)  (zreg + S_OFF);
    int*   cur  = (int*)  (zreg + S_CUR);
    int*   esrc = (int*)  (zreg + S_ESRC);
    float* ew   =          zreg + S_EW;
    __nv_bfloat16* wsp = (__nv_bfloat16*)(zreg + S_WSP);
    __nv_bfloat16* hch = (__nv_bfloat16*)(zreg + S_HCH);
    __nv_bfloat16* hcl = (__nv_bfloat16*)(zreg + S_HCL);
    float* h1   =          zreg + S_H1;
    __nv_bfloat16* e2h = (__nv_bfloat16*)(zreg + S_E2H);
    __nv_bfloat16* e2l = (__nv_bfloat16*)(zreg + S_E2L);
    __nv_bfloat16* zhi = (__nv_bfloat16*)(zreg + S_ZLH);
    float* klp  =          zreg + S_KLP;
    float* glp  =          zreg + S_GLP;
    float* outScalar = out + (size_t)out_size - 1;

    cudaFuncSetAttribute(loss_mma_kernel,
                         cudaFuncAttributeMaxDynamicSharedMemorySize, LOSS_SMEM);
    cudaFuncSetAttribute(gemm_bf16<true, false, false, 512>,
                         cudaFuncAttributeMaxDynamicSharedMemorySize, GW_SMEM);
    cudaFuncSetAttribute(gemm_bf16<true, true, true, 512>,
                         cudaFuncAttributeMaxDynamicSharedMemorySize, GW_SMEM);
    cudaFuncSetAttribute(heads_wmma<0>,
                         cudaFuncAttributeMaxDynamicSharedMemorySize, HD_SMEM);
    cudaFuncSetAttribute(heads_wmma<1>,
                         cudaFuncAttributeMaxDynamicSharedMemorySize, HD_SMEM);

    // CSR build + weight pre-split
    zero_deg_kernel<<<NN / 256, 256>>>(deg);
    hist_kernel<<<EE / 256, 256>>>(ei, deg);
    scan_kernel<<<1, 256>>>(deg, off, cur);
    fill_kernel<<<EE / 256, 256>>>(ei, w, cur, esrc, ew);
    split_w_kernel<<<131072 / 1024, 256>>>(W1, wsp + W1H, wsp + W1L, 131072);
    split_w_kernel<<<131072 / 1024, 256>>>(W2, wsp + W2H, wsp + W2L, 131072);
    split_w_kernel<<<65536 / 1024, 256>>>(W3, wsp + W3H, wsp + W3L, 65536);
    split_w_kernel<<<65536 / 1024, 256>>>(W4, wsp + W4H, wsp + W4L, 65536);

    // conv1 + linear1 + relu
    gather_kernel<<<NN, 256>>>(enc, hch, hcl, deg, off, esrc, ew);
    gemm_bf16<true, false, false, 512><<<dim3(4, 64), 256, GW_SMEM>>>(
        hch, hcl, wsp + W1H, wsp + W1L, b1, nullptr, h1, nullptr, nullptr);

    // conv2 + linear2 + relu + residual -> enc2 (+ split copies)
    gather_kernel<<<NN, 256>>>(h1, hch, hcl, deg, off, esrc, ew);
    gemm_bf16<true, true, true, 512><<<dim3(4, 64), 256, GW_SMEM>>>(
        hch, hcl, wsp + W2H, wsp + W2L, b2, enc, enc2, e2h, e2l);

    // fused heads (pre-split) -> Zl bf16 + KL partials
    heads_wmma<0><<<dim3(4, 64), 256, HD_SMEM>>>(
        nullptr, e2h, e2l, nullptr, nullptr,
        wsp + W3H, wsp + W3L, wsp + W4H, wsp + W4L,
        b3, b4, eps, nullptr, zhi, klp);

    // loss GEMM + BCE (128x128 tiles)
    loss_mma_kernel<<<dim3(64, 64), 256, LOSS_SMEM>>>(zhi, ADJ, glp);

    // loss scalar before Z overwrites partials
    finalize_kernel<<<1, 256>>>(klp, glp, outScalar);

    // final: write Z (self-splitting; reads only enc2/weights/eps)
    heads_wmma<1><<<dim3(4, 64), 256, HD_SMEM>>>(
        enc2, nullptr, nullptr, W3, W4,
        nullptr, nullptr, nullptr, nullptr,
        b3, b4, eps, zreg, nullptr, nullptr);
}

// round 12
// speedup vs baseline: 1.6060x; 1.0634x over previous
#include <cuda_runtime.h>
#include <cuda_bf16.h>
#include <mma.h>
#include <math.h>
#include <stdint.h>

using namespace nvcuda;

#define NN 8192
#define DD 256
#define EE 262144
#define KK 8

// ---- arena layout inside Z region of d_out (16,777,216 floats) ----
#define S_DEG   0
#define S_OFF   8192
#define S_CUR   16384
#define S_ESRC  24576
#define S_EW    286720
#define S_WSP   548864
#define S_HCH   1048576
#define S_HCL   3145728
#define S_H1    5242880
#define S_E2H   7340032
#define S_E2L   8388608
#define S_ZLH   9437184
#define S_KLP   10485760
#define S_GLP   10486016

// Z-row protection (Z row n occupies floats [n*2048, n*2048+2048)):
//  wsp:        floats [548864,1048576)   -> n in [256,512)   (rounded to 128)
//  e2h/e2l:    floats [7340032,9437184)  -> n in [3584,4608)
//  zhi/klp/glp:floats [9437184,10490112) -> n in [4608,5123)
// protected row-blocks: [256,512) and [3584,5248)
__device__ __forceinline__ bool row_protected(int rowBase) {
    return (rowBase >= 256 && rowBase < 512) || (rowBase >= 3584 && rowBase < 5248);
}

// pre-split weight offsets (bf16 units within wsp)
#define W1H 0
#define W1L 131072
#define W2H 262144
#define W2L 393216
#define W3H 524288
#define W3L 589824
#define W4H 655360
#define W4L 720896

// tiles / smem
#define LDA 136
#define LDW 72
#define LDC 72
#define GW_SMEM  106496
#define HLDA 72                         // heads A panel ld (K chunk 64 + pad)
#define HD_SMEM  73728                  // heads: Ah,Al(128x72) + 4 W panels(64x72); C reuses
#define LDC2 132
#define LOSS_SMEM 69632

// ================= CSR build =================
__global__ void zero_deg_kernel(int* deg) {
    deg[blockIdx.x * 256 + threadIdx.x] = 0;
}
__global__ void hist_kernel(const int* __restrict__ ei, int* deg) {
    int e = blockIdx.x * 256 + threadIdx.x;
    atomicAdd(&deg[ei[EE + e]], 1);
}
__global__ void scan_kernel(const int* __restrict__ deg, int* off, int* cur) {
    __shared__ int s[256];
    int tid = threadIdx.x;
    int base = tid * 32;
    int loc[32];
    int sum = 0;
#pragma unroll
    for (int i = 0; i < 32; i++) { loc[i] = deg[base + i]; sum += loc[i]; }
    s[tid] = sum;
    __syncthreads();
    for (int o = 1; o < 256; o <<= 1) {
        int v = (tid >= o) ? s[tid - o] : 0;
        __syncthreads();
        s[tid] += v;
        __syncthreads();
    }
    int run = s[tid] - sum;
#pragma unroll
    for (int i = 0; i < 32; i++) {
        off[base + i] = run;
        cur[base + i] = run;
        run += loc[i];
    }
}
__global__ void fill_kernel(const int* __restrict__ ei, const float* __restrict__ w,
                            int* cur, int* esrc, float* ew) {
    int e = blockIdx.x * 256 + threadIdx.x;
    int src = ei[e];
    int dst = ei[EE + e];
    int slot = atomicAdd(&cur[dst], 1);
    esrc[slot] = src;
    ew[slot]   = w[e];
}

// ================= one-shot fp32 -> bf16 hi/lo weight split =================
__global__ void split_w_kernel(const float* __restrict__ src,
                               __nv_bfloat16* __restrict__ h,
                               __nv_bfloat16* __restrict__ l, int n) {
    int i = (blockIdx.x * 256 + threadIdx.x) * 4;
    if (i >= n) return;
    float4 v = *(const float4*)(src + i);
    __nv_bfloat16 h0 = __float2bfloat16(v.x), h1 = __float2bfloat16(v.y);
    __nv_bfloat16 h2 = __float2bfloat16(v.z), h3 = __float2bfloat16(v.w);
    *(__nv_bfloat162*)(h + i)     = __nv_bfloat162(h0, h1);
    *(__nv_bfloat162*)(h + i + 2) = __nv_bfloat162(h2, h3);
    *(__nv_bfloat162*)(l + i) = __nv_bfloat162(
        __float2bfloat16(v.x - __bfloat162float(h0)),
        __float2bfloat16(v.y - __bfloat162float(h1)));
    *(__nv_bfloat162*)(l + i + 2) = __nv_bfloat162(
        __float2bfloat16(v.z - __bfloat162float(h2)),
        __float2bfloat16(v.w - __bfloat162float(h3)));
}

// ============ gather conv + combine, emitting split bf16 hcat ============
__global__ void gather_kernel(const float* __restrict__ x,
                              __nv_bfloat16* __restrict__ hch,
                              __nv_bfloat16* __restrict__ hcl,
                              const int* __restrict__ deg, const int* __restrict__ off,
                              const int* __restrict__ esrc, const float* __restrict__ ew) {
    __shared__ int   ss[256];
    __shared__ float sw[256];
    int n = blockIdx.x, d = threadIdx.x;
    int beg = off[n];
    int dg  = deg[n];
    float acc = 0.f;
    for (int c = 0; c < dg; c += 256) {
        int m = min(256, dg - c);
        if (d < m) { ss[d] = esrc[beg + c + d]; sw[d] = ew[beg + c + d]; }
        __syncthreads();
#pragma unroll 4
        for (int j = 0; j < m; j++)
            acc = fmaf(x[(size_t)ss[j] * DD + d], sw[j], acc);
        __syncthreads();
    }
    float xv = x[(size_t)n * DD + d];
    float av = acc / fmaxf((float)dg, 1.f);
    __nv_bfloat16 xh = __float2bfloat16(xv);
    __nv_bfloat16 ah = __float2bfloat16(av);
    int base = n * 512 + d;
    hch[base]       = xh;
    hch[base + 256] = ah;
    hcl[base]       = __float2bfloat16(xv - __bfloat162float(xh));
    hcl[base + 256] = __float2bfloat16(av - __bfloat162float(ah));
}

// ====== bf16 GEMM (pre-split inputs): C = act(A@W + b) (+res) (+split-out) ======
template<bool RELU, bool RES, bool SPLITOUT, int KD>
__global__ void __launch_bounds__(256, 2) gemm_bf16(
    const __nv_bfloat16* __restrict__ Ahg, const __nv_bfloat16* __restrict__ Alg,
    const __nv_bfloat16* __restrict__ Whg, const __nv_bfloat16* __restrict__ Wlg,
    const float* __restrict__ bias, const float* __restrict__ res,
    float* __restrict__ C, __nv_bfloat16* __restrict__ Ch, __nv_bfloat16* __restrict__ Cl) {
    extern __shared__ __align__(16) char sm[];
    __nv_bfloat16* Ah = (__nv_bfloat16*)sm;
    __nv_bfloat16* Al = Ah + 128 * LDA;
    __nv_bfloat16* Wh = Al + 128 * LDA;
    __nv_bfloat16* Wl = Wh + 128 * LDW;
    int tid = threadIdx.x, wid = tid >> 5;
    int wm0 = (wid >> 1) * 32, wn0 = (wid & 1) * 32;
    int rowBase = blockIdx.y * 128, colBase = blockIdx.x * 64;

    wmma::fragment<wmma::accumulator, 16, 16, 16, float> acc[2][2];
#pragma unroll
    for (int m = 0; m < 2; m++)
#pragma unroll
        for (int n = 0; n < 2; n++) wmma::fill_fragment(acc[m][n], 0.f);

    for (int kc = 0; kc < KD / 128; kc++) {
        int kg = kc * 128;
        for (int idx = tid; idx < 128 * 16; idx += 256) {
            int r = idx >> 4, c8 = (idx & 15) << 3;
            size_t g = (size_t)(rowBase + r) * KD + kg + c8;
            *(uint4*)&Ah[r * LDA + c8] = *(const uint4*)(Ahg + g);
            *(uint4*)&Al[r * LDA + c8] = *(const uint4*)(Alg + g);
        }
        for (int idx = tid; idx < 128 * 8; idx += 256) {
            int k = idx >> 3, c8 = (idx & 7) << 3;
            size_t g = (size_t)(kg + k) * 256 + colBase + c8;
            *(uint4*)&Wh[k * LDW + c8] = *(const uint4*)(Whg + g);
            *(uint4*)&Wl[k * LDW + c8] = *(const uint4*)(Wlg + g);
        }
        __syncthreads();
#pragma unroll
        for (int ks = 0; ks < 8; ks++) {
            int k0 = ks * 16;
            wmma::fragment<wmma::matrix_a, 16, 16, 16, __nv_bfloat16, wmma::row_major> aH[2], aL[2];
            wmma::fragment<wmma::matrix_b, 16, 16, 16, __nv_bfloat16, wmma::row_major> bH[2], bL[2];
#pragma unroll
            for (int m = 0; m < 2; m++) {
                wmma::load_matrix_sync(aH[m], &Ah[(wm0 + m * 16) * LDA + k0], LDA);
                wmma::load_matrix_sync(aL[m], &Al[(wm0 + m * 16) * LDA + k0], LDA);
            }
#pragma unroll
            for (int n = 0; n < 2; n++) {
                wmma::load_matrix_sync(bH[n], &Wh[k0 * LDW + wn0 + n * 16], LDW);
                wmma::load_matrix_sync(bL[n], &Wl[k0 * LDW + wn0 + n * 16], LDW);
            }
#pragma unroll
            for (int m = 0; m < 2; m++)
#pragma unroll
                for (int n = 0; n < 2; n++) {
                    wmma::mma_sync(acc[m][n], aH[m], bH[n], acc[m][n]);
                    wmma::mma_sync(acc[m][n], aL[m], bH[n], acc[m][n]);
                    wmma::mma_sync(acc[m][n], aH[m], bL[n], acc[m][n]);
                }
        }
        __syncthreads();
    }

    float* Cs = (float*)sm;
#pragma unroll
    for (int m = 0; m < 2; m++)
#pragma unroll
        for (int n = 0; n < 2; n++)
            wmma::store_matrix_sync(&Cs[(wm0 + m * 16) * LDC + wn0 + n * 16],
                                    acc[m][n], LDC, wmma::mem_row_major);
    __syncthreads();

#pragma unroll
    for (int rb = 0; rb < 8; rb++) {
        int r = rb * 16 + (tid >> 4);
        int c = (tid & 15) << 2;
        float4 o = *(float4*)&Cs[r * LDC + c];
        float4 bv = *(const float4*)(bias + colBase + c);
        o.x += bv.x; o.y += bv.y; o.z += bv.z; o.w += bv.w;
        if (RELU) {
            o.x = fmaxf(o.x, 0.f); o.y = fmaxf(o.y, 0.f);
            o.z = fmaxf(o.z, 0.f); o.w = fmaxf(o.w, 0.f);
        }
        if (RES) {
            float4 rv = *(const float4*)(res + (size_t)(rowBase + r) * 256 + colBase + c);
            o.x += rv.x; o.y += rv.y; o.z += rv.z; o.w += rv.w;
        }
        size_t gidx = (size_t)(rowBase + r) * 256 + colBase + c;
        *(float4*)(C + gidx) = o;
        if (SPLITOUT) {
            __nv_bfloat16 h0 = __float2bfloat16(o.x), h1 = __float2bfloat16(o.y);
            __nv_bfloat16 h2 = __float2bfloat16(o.z), h3 = __float2bfloat16(o.w);
            *(__nv_bfloat162*)(Ch + gidx)     = __nv_bfloat162(h0, h1);
            *(__nv_bfloat162*)(Ch + gidx + 2) = __nv_bfloat162(h2, h3);
            *(__nv_bfloat162*)(Cl + gidx) = __nv_bfloat162(
                __float2bfloat16(o.x - __bfloat162float(h0)),
                __float2bfloat16(o.y - __bfloat162float(h1)));
            *(__nv_bfloat162*)(Cl + gidx + 2) = __nv_bfloat162(
                __float2bfloat16(o.z - __bfloat162float(h2)),
                __float2bfloat16(o.w - __bfloat162float(h3)));
        }
    }
}

__device__ __forceinline__ void split4s(__nv_bfloat16* H, __nv_bfloat16* L, int off, float4 v) {
    __nv_bfloat16 h0 = __float2bfloat16(v.x), h1 = __float2bfloat16(v.y);
    __nv_bfloat16 h2 = __float2bfloat16(v.z), h3 = __float2bfloat16(v.w);
    *(__nv_bfloat162*)(H + off)     = __nv_bfloat162(h0, h1);
    *(__nv_bfloat162*)(H + off + 2) = __nv_bfloat162(h2, h3);
    *(__nv_bfloat162*)(L + off) = __nv_bfloat162(
        __float2bfloat16(v.x - __bfloat162float(h0)),
        __float2bfloat16(v.y - __bfloat162float(h1)));
    *(__nv_bfloat162*)(L + off + 2) = __nv_bfloat162(
        __float2bfloat16(v.z - __bfloat162float(h2)),
        __float2bfloat16(v.w - __bfloat162float(h3)));
}

// ====== heads: dual GEMM (mu, lv). K-chunk 64, occ 2.
// MODE 0: pre-split inputs; writes Z for non-protected rows + Zl + KL partials.
// MODE 1: cleanup for protected rows; fp32 inputs (self-split); writes Z only.
template<int MODE>
__global__ void __launch_bounds__(256, 2) heads_wmma(
    const float* __restrict__ enc2f,
    const __nv_bfloat16* __restrict__ e2h, const __nv_bfloat16* __restrict__ e2l,
    const float* __restrict__ W3f, const float* __restrict__ W4f,
    const __nv_bfloat16* __restrict__ W3h, const __nv_bfloat16* __restrict__ W3l,
    const __nv_bfloat16* __restrict__ W4h, const __nv_bfloat16* __restrict__ W4l,
    const float* __restrict__ b3, const float* __restrict__ b4,
    const float* __restrict__ eps,
    float* __restrict__ dstZ, __nv_bfloat16* __restrict__ zhi,
    float* __restrict__ klpart) {
    extern __shared__ __align__(16) char sm[];
    __nv_bfloat16* Ah  = (__nv_bfloat16*)sm;       // 128 x HLDA
    __nv_bfloat16* Al  = Ah + 128 * HLDA;
    __nv_bfloat16* P3h = Al + 128 * HLDA;          // 64 x LDW each
    __nv_bfloat16* P3l = P3h + 64 * LDW;
    __nv_bfloat16* P4h = P3l + 64 * LDW;
    __nv_bfloat16* P4l = P4h + 64 * LDW;
    int tid = threadIdx.x, wid = tid >> 5;
    int wm0 = (wid >> 1) * 32, wn0 = (wid & 1) * 32;
    int rowBase;
    if (MODE == 0) rowBase = blockIdx.y * 128;
    else           rowBase = (blockIdx.y < 2) ? 256 + blockIdx.y * 128
                                              : 3584 + (blockIdx.y - 2) * 128;
    int colBase = blockIdx.x * 64;

    wmma::fragment<wmma::accumulator, 16, 16, 16, float> ac3[2][2], ac4[2][2];
#pragma unroll
    for (int m = 0; m < 2; m++)
#pragma unroll
        for (int n = 0; n < 2; n++) {
            wmma::fill_fragment(ac3[m][n], 0.f);
            wmma::fill_fragment(ac4[m][n], 0.f);
        }

    for (int kc = 0; kc < 4; kc++) {
        int kg = kc * 64;
        if (MODE == 0) {
            for (int idx = tid; idx < 128 * 8; idx += 256) {
                int r = idx >> 3, c8 = (idx & 7) << 3;
                size_t g = (size_t)(rowBase + r) * 256 + kg + c8;
                *(uint4*)&Ah[r * HLDA + c8] = *(const uint4*)(e2h + g);
                *(uint4*)&Al[r * HLDA + c8] = *(const uint4*)(e2l + g);
            }
            for (int idx = tid; idx < 64 * 8; idx += 256) {
                int k = idx >> 3, c8 = (idx & 7) << 3;
                size_t g = (size_t)(kg + k) * 256 + colBase + c8;
                *(uint4*)&P3h[k * LDW + c8] = *(const uint4*)(W3h + g);
                *(uint4*)&P3l[k * LDW + c8] = *(const uint4*)(W3l + g);
                *(uint4*)&P4h[k * LDW + c8] = *(const uint4*)(W4h + g);
                *(uint4*)&P4l[k * LDW + c8] = *(const uint4*)(W4l + g);
            }
        } else {
            for (int idx = tid; idx < 128 * 16; idx += 256) {
                int r = idx >> 4, c4 = (idx & 15) << 2;
                float4 v = *(const float4*)(enc2f + (size_t)(rowBase + r) * 256 + kg + c4);
                split4s(Ah, Al, r * HLDA + c4, v);
            }
            for (int idx = tid; idx < 64 * 16; idx += 256) {
                int k = idx >> 4, c4 = (idx & 15) << 2;
                size_t g = (size_t)(kg + k) * 256 + colBase + c4;
                split4s(P3h, P3l, k * LDW + c4, *(const float4*)(W3f + g));
                split4s(P4h, P4l, k * LDW + c4, *(const float4*)(W4f + g));
            }
        }
        __syncthreads();
#pragma unroll
        for (int ks = 0; ks < 4; ks++) {
            int k0 = ks * 16;
            wmma::fragment<wmma::matrix_a, 16, 16, 16, __nv_bfloat16, wmma::row_major> aH[2], aL[2];
#pragma unroll
            for (int m = 0; m < 2; m++) {
                wmma::load_matrix_sync(aH[m], &Ah[(wm0 + m * 16) * HLDA + k0], HLDA);
                wmma::load_matrix_sync(aL[m], &Al[(wm0 + m * 16) * HLDA + k0], HLDA);
            }
            {
                wmma::fragment<wmma::matrix_b, 16, 16, 16, __nv_bfloat16, wmma::row_major> bH[2], bL[2];
#pragma unroll
                for (int n = 0; n < 2; n++) {
                    wmma::load_matrix_sync(bH[n], &P3h[k0 * LDW + wn0 + n * 16], LDW);
                    wmma::load_matrix_sync(bL[n], &P3l[k0 * LDW + wn0 + n * 16], LDW);
                }
#pragma unroll
                for (int m = 0; m < 2; m++)
#pragma unroll
                    for (int n = 0; n < 2; n++) {
                        wmma::mma_sync(ac3[m][n], aH[m], bH[n], ac3[m][n]);
                        wmma::mma_sync(ac3[m][n], aL[m], bH[n], ac3[m][n]);
                        wmma::mma_sync(ac3[m][n], aH[m], bL[n], ac3[m][n]);
                    }
            }
            {
                wmma::fragment<wmma::matrix_b, 16, 16, 16, __nv_bfloat16, wmma::row_major> bH[2], bL[2];
#pragma unroll
                for (int n = 0; n < 2; n++) {
                    wmma::load_matrix_sync(bH[n], &P4h[k0 * LDW + wn0 + n * 16], LDW);
                    wmma::load_matrix_sync(bL[n], &P4l[k0 * LDW + wn0 + n * 16], LDW);
                }
#pragma unroll
                for (int m = 0; m < 2; m++)
#pragma unroll
                    for (int n = 0; n < 2; n++) {
                        wmma::mma_sync(ac4[m][n], aH[m], bH[n], ac4[m][n]);
                        wmma::mma_sync(ac4[m][n], aL[m], bH[n], ac4[m][n]);
                        wmma::mma_sync(ac4[m][n], aH[m], bL[n], ac4[m][n]);
                    }
            }
        }
        __syncthreads();
    }

    float* Cmu = (float*)sm;                 // 128 x LDC (reuses panels)
    float* Clv = Cmu + 128 * LDC;
#pragma unroll
    for (int m = 0; m < 2; m++)
#pragma unroll
        for (int n = 0; n < 2; n++) {
            wmma::store_matrix_sync(&Cmu[(wm0 + m * 16) * LDC + wn0 + n * 16],
                                    ac3[m][n], LDC, wmma::mem_row_major);
            wmma::store_matrix_sync(&Clv[(wm0 + m * 16) * LDC + wn0 + n * 16],
                                    ac4[m][n], LDC, wmma::mem_row_major);
        }
    __syncthreads();

    bool zwrite = (MODE == 1) || !row_protected(rowBase);
    float klsum = 0.f;
#pragma unroll
    for (int rb = 0; rb < 8; rb++) {
        int r = rb * 16 + (tid >> 4);
        int c = (tid & 15) << 2;
        int n = rowBase + r;
        int col = colBase + c;
        float4 mu4 = *(float4*)&Cmu[r * LDC + c];
        float4 lv4 = *(float4*)&Clv[r * LDC + c];
        float4 b3v = *(const float4*)(b3 + col);
        float4 b4v = *(const float4*)(b4 + col);
        float mu[4] = {mu4.x + b3v.x, mu4.y + b3v.y, mu4.z + b3v.z, mu4.w + b3v.w};
        float lv[4] = {lv4.x + b4v.x, lv4.y + b4v.y, lv4.z + b4v.z, lv4.w + b4v.w};
        float sg[4];
#pragma unroll
        for (int j = 0; j < 4; j++) sg[j] = __expf(0.5f * lv[j]);

        float4 es = make_float4(0.f, 0.f, 0.f, 0.f);
#pragma unroll
        for (int k = 0; k < KK; k++) {
            float4 e = *(const float4*)(eps + (size_t)(n * KK + k) * DD + col);
            if (MODE == 0) { es.x += e.x; es.y += e.y; es.z += e.z; es.w += e.w; }
            if (zwrite) {
                float4 o;
                o.x = fmaf(sg[0], e.x, mu[0]);
                o.y = fmaf(sg[1], e.y, mu[1]);
                o.z = fmaf(sg[2], e.z, mu[2]);
                o.w = fmaf(sg[3], e.w, mu[3]);
                *(float4*)(dstZ + (size_t)(n * KK + k) * DD + col) = o;
            }
        }
        if (MODE == 0) {
            float zv[4];
            zv[0] = fmaf(sg[0], es.x * 0.125f, mu[0]);
            zv[1] = fmaf(sg[1], es.y * 0.125f, mu[1]);
            zv[2] = fmaf(sg[2], es.z * 0.125f, mu[2]);
            zv[3] = fmaf(sg[3], es.w * 0.125f, mu[3]);
            size_t base = (size_t)n * DD + col;
            *(__nv_bfloat162*)(zhi + base) =
                __nv_bfloat162(__float2bfloat16(zv[0]), __float2bfloat16(zv[1]));
            *(__nv_bfloat162*)(zhi + base + 2) =
                __nv_bfloat162(__float2bfloat16(zv[2]), __float2bfloat16(zv[3]));
#pragma unroll
            for (int j = 0; j < 4; j++)
                klsum += 1.f + lv[j] - mu[j] * mu[j] - sg[j] * sg[j];
        }
    }

    if (MODE == 0) {
        __shared__ float sred[256];
        sred[tid] = klsum; __syncthreads();
        for (int s = 128; s > 0; s >>= 1) {
            if (tid < s) sred[tid] += sred[tid + s];
            __syncthreads();
        }
        if (tid == 0) klpart[blockIdx.y * 4 + blockIdx.x] = sred[0];
    }
}

// ====== WMMA bf16 loss: Zl@Zl^T + BCE, 128x128 tiles ======
__global__ void __launch_bounds__(256, 2) loss_mma_kernel(
    const __nv_bfloat16* __restrict__ zhi,
    const float* __restrict__ ADJ, float* __restrict__ glpart) {
    int bi = blockIdx.y, bj = blockIdx.x;
    int tid = threadIdx.x;
    if (bj < bi) {
        if (tid == 0) glpart[bi * 64 + bj] = 0.f;
        return;
    }
    int rowBase = bi * 128, colBase = bj * 128;

    extern __shared__ __align__(16) char smc[];
    __nv_bfloat16* AH = (__nv_bfloat16*)smc;
    __nv_bfloat16* BH = AH + 128 * LDA;

    int wid = tid >> 5;
    int wm0 = (wid >> 1) * 32;
    int wn0 = (wid & 1) * 64;

    wmma::fragment<wmma::accumulator, 16, 16, 16, float> acc[2][4];
#pragma unroll
    for (int m = 0; m < 2; m++)
#pragma unroll
        for (int n = 0; n < 4; n++) wmma::fill_fragment(acc[m][n], 0.f);

    for (int kc = 0; kc < 2; kc++) {
        int kg = kc * 128;
        for (int idx = tid; idx < 128 * 16; idx += 256) {
            int r = idx >> 4, c8 = (idx & 15) << 3;
            *(uint4*)&AH[r * LDA + c8] =
                *(const uint4*)(zhi + (size_t)(rowBase + r) * 256 + kg + c8);
            *(uint4*)&BH[r * LDA + c8] =
                *(const uint4*)(zhi + (size_t)(colBase + r) * 256 + kg + c8);
        }
        __syncthreads();
#pragma unroll
        for (int ks = 0; ks < 8; ks++) {
            int k0 = ks * 16;
            wmma::fragment<wmma::matrix_a, 16, 16, 16, __nv_bfloat16, wmma::row_major> aH[2];
#pragma unroll
            for (int m = 0; m < 2; m++)
                wmma::load_matrix_sync(aH[m], &AH[(wm0 + m * 16) * LDA + k0], LDA);
#pragma unroll
            for (int n = 0; n < 4; n++) {
                wmma::fragment<wmma::matrix_b, 16, 16, 16, __nv_bfloat16, wmma::col_major> bH;
                wmma::load_matrix_sync(bH, &BH[(wn0 + n * 16) * LDA + k0], LDA);
#pragma unroll
                for (int m = 0; m < 2; m++)
                    wmma::mma_sync(acc[m][n], aH[m], bH, acc[m][n]);
            }
        }
        __syncthreads();
    }

    float* Cs = (float*)smc;
#pragma unroll
    for (int m = 0; m < 2; m++)
#pragma unroll
        for (int n = 0; n < 4; n++)
            wmma::store_matrix_sync(&Cs[(wm0 + m * 16) * LDC2 + wn0 + n * 16],
                                    acc[m][n], LDC2, wmma::mem_row_major);
    __syncthreads();

    float term = 0.f;
    {
        int jl = tid & 127;
        int j = colBase + jl;
        for (int il = tid >> 7; il < 128; il += 2) {
            int i = rowBase + il;
            if (i > j) continue;
            float c = Cs[il * LDC2 + jl];
            float sp = fmaxf(c, 0.f) + __logf(1.f + __expf(-fabsf(c)));
            float a = ADJ[(size_t)i * NN + j];
            term += (i < j ? 2.f : 1.f) * sp - c * a;
        }
    }
    {
        int il = tid & 127;
        int i = rowBase + il;
        for (int jl = tid >> 7; jl < 128; jl += 2) {
            int j = colBase + jl;
            if (i < j)
                term -= Cs[il * LDC2 + jl] * ADJ[(size_t)j * NN + i];
        }
    }

    __shared__ float sred[256];
    sred[tid] = term; __syncthreads();
    for (int s = 128; s > 0; s >>= 1) {
        if (tid < s) sred[tid] += sred[tid + s];
        __syncthreads();
    }
    if (tid == 0) glpart[bi * 64 + bj] = sred[0];
}

// ================= final reduction =================
__global__ void finalize_kernel(const float* __restrict__ klpart,
                                const float* __restrict__ glpart,
                                float* __restrict__ outScalar) {
    __shared__ double sk[256], sg[256];
    int t = threadIdx.x;
    double a = (double)klpart[t];
    double b = 0.0;
    for (int i = t; i < 4096; i += 256) b += (double)glpart[i];
    sk[t] = a; sg[t] = b; __syncthreads();
    for (int s = 128; s > 0; s >>= 1) {
        if (t < s) { sk[t] += sk[t + s]; sg[t] += sg[t + s]; }
        __syncthreads();
    }
    if (t == 0) {
        double kl = -0.5 * sk[0] / (double)NN;
        double gl = sg[0] / ((double)NN * (double)NN);
        *outScalar = (float)(kl + gl);
    }
}

// ================= host launcher =================
extern "C" void kernel_launch(void* const* d_in, const int* in_sizes, int n_in,
                              void* d_out, int out_size) {
    const float* enc = (const float*)d_in[0];
    const int*   ei  = (const int*)d_in[1];
    const float* w   = (const float*)d_in[2];
    const float* ADJ = (const float*)d_in[3];
    const float* eps = (const float*)d_in[4];
    const float* W1 = (const float*)d_in[5];  const float* b1 = (const float*)d_in[6];
    const float* W2 = (const float*)d_in[7];  const float* b2 = (const float*)d_in[8];
    const float* W3 = (const float*)d_in[9];  const float* b3 = (const float*)d_in[10];
    const float* W4 = (const float*)d_in[11]; const float* b4 = (const float*)d_in[12];

    float* out  = (float*)d_out;
    float* enc2 = out;
    float* zreg = out + (size_t)NN * DD;

    int*   deg  = (int*)  (zreg + S_DEG);
    int*   off  = (int*)  (zreg + S_OFF);
    int*   cur  = (int*)  (zreg + S_CUR);
    int*   esrc = (int*)  (zreg + S_ESRC);
    float* ew   =          zreg + S_EW;
    __nv_bfloat16* wsp = (__nv_bfloat16*)(zreg + S_WSP);
    __nv_bfloat16* hch = (__nv_bfloat16*)(zreg + S_HCH);
    __nv_bfloat16* hcl = (__nv_bfloat16*)(zreg + S_HCL);
    float* h1   =          zreg + S_H1;
    __nv_bfloat16* e2h = (__nv_bfloat16*)(zreg + S_E2H);
    __nv_bfloat16* e2l = (__nv_bfloat16*)(zreg + S_E2L);
    __nv_bfloat16* zhi = (__nv_bfloat16*)(zreg + S_ZLH);
    float* klp  =          zreg + S_KLP;
    float* glp  =          zreg + S_GLP;
    float* outScalar = out + (size_t)out_size - 1;

    cudaFuncSetAttribute(loss_mma_kernel,
                         cudaFuncAttributeMaxDynamicSharedMemorySize, LOSS_SMEM);
    cudaFuncSetAttribute(gemm_bf16<true, false, false, 512>,
                         cudaFuncAttributeMaxDynamicSharedMemorySize, GW_SMEM);
    cudaFuncSetAttribute(gemm_bf16<true, true, true, 512>,
                         cudaFuncAttributeMaxDynamicSharedMemorySize, GW_SMEM);
    cudaFuncSetAttribute(heads_wmma<0>,
                         cudaFuncAttributeMaxDynamicSharedMemorySize, HD_SMEM);
    cudaFuncSetAttribute(heads_wmma<1>,
                         cudaFuncAttributeMaxDynamicSharedMemorySize, HD_SMEM);

    // CSR build + weight pre-split
    zero_deg_kernel<<<NN / 256, 256>>>(deg);
    hist_kernel<<<EE / 256, 256>>>(ei, deg);
    scan_kernel<<<1, 256>>>(deg, off, cur);
    fill_kernel<<<EE / 256, 256>>>(ei, w, cur, esrc, ew);
    split_w_kernel<<<131072 / 1024, 256>>>(W1, wsp + W1H, wsp + W1L, 131072);
    split_w_kernel<<<131072 / 1024, 256>>>(W2, wsp + W2H, wsp + W2L, 131072);
    split_w_kernel<<<65536 / 1024, 256>>>(W3, wsp + W3H, wsp + W3L, 65536);
    split_w_kernel<<<65536 / 1024, 256>>>(W4, wsp + W4H, wsp + W4L, 65536);

    // conv1 + linear1 + relu
    gather_kernel<<<NN, 256>>>(enc, hch, hcl, deg, off, esrc, ew);
    gemm_bf16<true, false, false, 512><<<dim3(4, 64), 256, GW_SMEM>>>(
        hch, hcl, wsp + W1H, wsp + W1L, b1, nullptr, h1, nullptr, nullptr);

    // conv2 + linear2 + relu + residual -> enc2 (+ split copies)
    gather_kernel<<<NN, 256>>>(h1, hch, hcl, deg, off, esrc, ew);
    gemm_bf16<true, true, true, 512><<<dim3(4, 64), 256, GW_SMEM>>>(
        hch, hcl, wsp + W2H, wsp + W2L, b2, enc, enc2, e2h, e2l);

    // heads: dual GEMM -> Zl + KL partials + Z for non-protected rows
    heads_wmma<0><<<dim3(4, 64), 256, HD_SMEM>>>(
        nullptr, e2h, e2l, nullptr, nullptr,
        wsp + W3H, wsp + W3L, wsp + W4H, wsp + W4L,
        b3, b4, eps, zreg, zhi, klp);

    // loss GEMM + BCE
    loss_mma_kernel<<<dim3(64, 64), 256, LOSS_SMEM>>>(zhi, ADJ, glp);

    // loss scalar (reads klp/glp before cleanup overwrites them)
    finalize_kernel<<<1, 256>>>(klp, glp, outScalar);

    // cleanup: write Z for the 15 protected row-blocks (self-splitting)
    heads_wmma<1><<<dim3(4, 15), 256, HD_SMEM>>>(
        enc2, nullptr, nullptr, W3, W4,
        nullptr, nullptr, nullptr, nullptr,
        b3, b4, eps, zreg, nullptr, nullptr);
}

// round 13
// speedup vs baseline: 2.0679x; 1.2876x over previous
#include <cuda_runtime.h>
#include <cuda_bf16.h>
#include <mma.h>
#include <math.h>
#include <stdint.h>

using namespace nvcuda;

#define NN 8192
#define DD 256
#define EE 262144
#define KK 8

// ---- arena layout inside Z region of d_out (16,777,216 floats) ----
#define S_DEG   0
#define S_OFF   8192
#define S_CUR   16384
#define S_ESRC  24576
#define S_EW    286720
#define S_WSP   548864
#define S_HCH   1048576
#define S_HCL   3145728
#define S_H1    5242880
#define S_E2H   7340032
#define S_E2L   8388608
#define S_ZLH   9437184
#define S_KLP   10485760
#define S_GLP   10486016

// protected Z row-blocks: [256,512) and [3584,5248)
__device__ __forceinline__ bool row_protected(int rowBase) {
    return (rowBase >= 256 && rowBase < 512) || (rowBase >= 3584 && rowBase < 5248);
}

// pre-split weight offsets (bf16 units within wsp)
#define W1H 0
#define W1L 131072
#define W2H 262144
#define W2L 393216
#define W3H 524288
#define W3L 589824
#define W4H 655360
#define W4L 720896

// tiles / smem
#define HLDA 72                         // A panel ld (K-chunk 64 + pad)
#define LDW 72                          // heads W panel ld (64 n + pad)
#define LDW2 136                        // gemm W panel ld (128 n + pad)
#define LDC 72
#define LDCG 136                        // gemm C smem ld (128 n + pad)
#define GW_SMEM  71680                  // Ah,Al(128x72) + Wh,Wl(64x136)
#define HD_SMEM  73728
#define LDC2 132
#define LOSS_SMEM 69632
#define LDA 136                         // loss panel ld (K chunk 128 + pad)

// ================= CSR build =================
__global__ void hist_kernel(const int* __restrict__ ei, int* deg) {
    int e = blockIdx.x * 256 + threadIdx.x;
    atomicAdd(&deg[ei[EE + e]], 1);
}
__global__ void scan_kernel(const int* __restrict__ deg, int* off, int* cur) {
    __shared__ int s[256];
    int tid = threadIdx.x;
    int base = tid * 32;
    int loc[32];
    int sum = 0;
#pragma unroll
    for (int i = 0; i < 32; i++) { loc[i] = deg[base + i]; sum += loc[i]; }
    s[tid] = sum;
    __syncthreads();
    for (int o = 1; o < 256; o <<= 1) {
        int v = (tid >= o) ? s[tid - o] : 0;
        __syncthreads();
        s[tid] += v;
        __syncthreads();
    }
    int run = s[tid] - sum;
#pragma unroll
    for (int i = 0; i < 32; i++) {
        off[base + i] = run;
        cur[base + i] = run;
        run += loc[i];
    }
}
__global__ void fill_kernel(const int* __restrict__ ei, const float* __restrict__ w,
                            int* cur, int* esrc, float* ew) {
    int e = blockIdx.x * 256 + threadIdx.x;
    int src = ei[e];
    int dst = ei[EE + e];
    int slot = atomicAdd(&cur[dst], 1);
    esrc[slot] = src;
    ew[slot]   = w[e];
}

// ============ fused: zero deg + split all 4 weights (one launch) ============
__global__ void split_w_all(const float* __restrict__ W1, const float* __restrict__ W2,
                            const float* __restrict__ W3, const float* __restrict__ W4,
                            __nv_bfloat16* __restrict__ wsp, int* __restrict__ deg) {
    int gid = blockIdx.x * 256 + threadIdx.x;    // 384 blocks x 256 = 98304 threads
    if (gid < NN) deg[gid] = 0;
    int idx4 = gid * 4;
    const float* src;
    int local;
    __nv_bfloat16 *dh, *dl;
    if (idx4 < 131072)      { src = W1; local = idx4;          dh = wsp + W1H; dl = wsp + W1L; }
    else if (idx4 < 262144) { src = W2; local = idx4 - 131072; dh = wsp + W2H; dl = wsp + W2L; }
    else if (idx4 < 327680) { src = W3; local = idx4 - 262144; dh = wsp + W3H; dl = wsp + W3L; }
    else                    { src = W4; local = idx4 - 327680; dh = wsp + W4H; dl = wsp + W4L; }
    float4 v = *(const float4*)(src + local);
    __nv_bfloat16 h0 = __float2bfloat16(v.x), h1 = __float2bfloat16(v.y);
    __nv_bfloat16 h2 = __float2bfloat16(v.z), h3 = __float2bfloat16(v.w);
    *(__nv_bfloat162*)(dh + local)     = __nv_bfloat162(h0, h1);
    *(__nv_bfloat162*)(dh + local + 2) = __nv_bfloat162(h2, h3);
    *(__nv_bfloat162*)(dl + local) = __nv_bfloat162(
        __float2bfloat16(v.x - __bfloat162float(h0)),
        __float2bfloat16(v.y - __bfloat162float(h1)));
    *(__nv_bfloat162*)(dl + local + 2) = __nv_bfloat162(
        __float2bfloat16(v.z - __bfloat162float(h2)),
        __float2bfloat16(v.w - __bfloat162float(h3)));
}

// ============ gather conv + combine, emitting split bf16 hcat ============
__global__ void gather_kernel(const float* __restrict__ x,
                              __nv_bfloat16* __restrict__ hch,
                              __nv_bfloat16* __restrict__ hcl,
                              const int* __restrict__ deg, const int* __restrict__ off,
                              const int* __restrict__ esrc, const float* __restrict__ ew) {
    __shared__ int   ss[256];
    __shared__ float sw[256];
    int n = blockIdx.x, d = threadIdx.x;
    int beg = off[n];
    int dg  = deg[n];
    float acc = 0.f;
    for (int c = 0; c < dg; c += 256) {
        int m = min(256, dg - c);
        if (d < m) { ss[d] = esrc[beg + c + d]; sw[d] = ew[beg + c + d]; }
        __syncthreads();
#pragma unroll 4
        for (int j = 0; j < m; j++)
            acc = fmaf(x[(size_t)ss[j] * DD + d], sw[j], acc);
        __syncthreads();
    }
    float xv = x[(size_t)n * DD + d];
    float av = acc / fmaxf((float)dg, 1.f);
    __nv_bfloat16 xh = __float2bfloat16(xv);
    __nv_bfloat16 ah = __float2bfloat16(av);
    int base = n * 512 + d;
    hch[base]       = xh;
    hch[base + 256] = ah;
    hcl[base]       = __float2bfloat16(xv - __bfloat162float(xh));
    hcl[base + 256] = __float2bfloat16(av - __bfloat162float(ah));
}

// ====== bf16 GEMM, N-tile 128, K-chunk 64: C = act(A@W + b) (+res) (+split-out) ======
template<bool RELU, bool RES, bool SPLITOUT, int KD>
__global__ void __launch_bounds__(256, 2) gemm_bf16(
    const __nv_bfloat16* __restrict__ Ahg, const __nv_bfloat16* __restrict__ Alg,
    const __nv_bfloat16* __restrict__ Whg, const __nv_bfloat16* __restrict__ Wlg,
    const float* __restrict__ bias, const float* __restrict__ res,
    float* __restrict__ C, __nv_bfloat16* __restrict__ Ch, __nv_bfloat16* __restrict__ Cl) {
    extern __shared__ __align__(16) char sm[];
    __nv_bfloat16* Ah = (__nv_bfloat16*)sm;        // 128 x HLDA
    __nv_bfloat16* Al = Ah + 128 * HLDA;
    __nv_bfloat16* Wh = Al + 128 * HLDA;           // 64 x LDW2
    __nv_bfloat16* Wl = Wh + 64 * LDW2;
    int tid = threadIdx.x, wid = tid >> 5;
    int wm0 = (wid & 3) * 32, wn0 = (wid >> 2) * 64;
    int rowBase = blockIdx.y * 128, colBase = blockIdx.x * 128;

    wmma::fragment<wmma::accumulator, 16, 16, 16, float> acc[2][4];
#pragma unroll
    for (int m = 0; m < 2; m++)
#pragma unroll
        for (int n = 0; n < 4; n++) wmma::fill_fragment(acc[m][n], 0.f);

    for (int kc = 0; kc < KD / 64; kc++) {
        int kg = kc * 64;
        for (int idx = tid; idx < 128 * 8; idx += 256) {
            int r = idx >> 3, c8 = (idx & 7) << 3;
            size_t g = (size_t)(rowBase + r) * KD + kg + c8;
            *(uint4*)&Ah[r * HLDA + c8] = *(const uint4*)(Ahg + g);
            *(uint4*)&Al[r * HLDA + c8] = *(const uint4*)(Alg + g);
        }
        for (int idx = tid; idx < 64 * 16; idx += 256) {
            int k = idx >> 4, c8 = (idx & 15) << 3;
            size_t g = (size_t)(kg + k) * 256 + colBase + c8;
            *(uint4*)&Wh[k * LDW2 + c8] = *(const uint4*)(Whg + g);
            *(uint4*)&Wl[k * LDW2 + c8] = *(const uint4*)(Wlg + g);
        }
        __syncthreads();
#pragma unroll
        for (int ks = 0; ks < 4; ks++) {
            int k0 = ks * 16;
            wmma::fragment<wmma::matrix_a, 16, 16, 16, __nv_bfloat16, wmma::row_major> aH[2], aL[2];
#pragma unroll
            for (int m = 0; m < 2; m++) {
                wmma::load_matrix_sync(aH[m], &Ah[(wm0 + m * 16) * HLDA + k0], HLDA);
                wmma::load_matrix_sync(aL[m], &Al[(wm0 + m * 16) * HLDA + k0], HLDA);
            }
#pragma unroll
            for (int n = 0; n < 4; n++) {
                wmma::fragment<wmma::matrix_b, 16, 16, 16, __nv_bfloat16, wmma::row_major> bH, bL;
                wmma::load_matrix_sync(bH, &Wh[k0 * LDW2 + wn0 + n * 16], LDW2);
                wmma::load_matrix_sync(bL, &Wl[k0 * LDW2 + wn0 + n * 16], LDW2);
#pragma unroll
                for (int m = 0; m < 2; m++) {
                    wmma::mma_sync(acc[m][n], aH[m], bH, acc[m][n]);
                    wmma::mma_sync(acc[m][n], aL[m], bH, acc[m][n]);
                    wmma::mma_sync(acc[m][n], aH[m], bL, acc[m][n]);
                }
            }
        }
        __syncthreads();
    }

    float* Cs = (float*)sm;   // 128 x LDCG fp32 (69,632 B <= 71,680)
#pragma unroll
    for (int m = 0; m < 2; m++)
#pragma unroll
        for (int n = 0; n < 4; n++)
            wmma::store_matrix_sync(&Cs[(wm0 + m * 16) * LDCG + wn0 + n * 16],
                                    acc[m][n], LDCG, wmma::mem_row_major);
    __syncthreads();

#pragma unroll
    for (int rb = 0; rb < 8; rb++) {
        int r = rb * 16 + (tid >> 4);
        int c8 = (tid & 15) << 3;
#pragma unroll
        for (int q = 0; q < 2; q++) {
            int c = c8 + q * 4;
            float4 o = *(float4*)&Cs[r * LDCG + c];
            float4 bv = *(const float4*)(bias + colBase + c);
            o.x += bv.x; o.y += bv.y; o.z += bv.z; o.w += bv.w;
            if (RELU) {
                o.x = fmaxf(o.x, 0.f); o.y = fmaxf(o.y, 0.f);
                o.z = fmaxf(o.z, 0.f); o.w = fmaxf(o.w, 0.f);
            }
            if (RES) {
                float4 rv = *(const float4*)(res + (size_t)(rowBase + r) * 256 + colBase + c);
                o.x += rv.x; o.y += rv.y; o.z += rv.z; o.w += rv.w;
            }
            size_t gidx = (size_t)(rowBase + r) * 256 + colBase + c;
            *(float4*)(C + gidx) = o;
            if (SPLITOUT) {
                __nv_bfloat16 h0 = __float2bfloat16(o.x), h1 = __float2bfloat16(o.y);
                __nv_bfloat16 h2 = __float2bfloat16(o.z), h3 = __float2bfloat16(o.w);
                *(__nv_bfloat162*)(Ch + gidx)     = __nv_bfloat162(h0, h1);
                *(__nv_bfloat162*)(Ch + gidx + 2) = __nv_bfloat162(h2, h3);
                *(__nv_bfloat162*)(Cl + gidx) = __nv_bfloat162(
                    __float2bfloat16(o.x - __bfloat162float(h0)),
                    __float2bfloat16(o.y - __bfloat162float(h1)));
                *(__nv_bfloat162*)(Cl + gidx + 2) = __nv_bfloat162(
                    __float2bfloat16(o.z - __bfloat162float(h2)),
                    __float2bfloat16(o.w - __bfloat162float(h3)));
            }
        }
    }
}

__device__ __forceinline__ void split4s(__nv_bfloat16* H, __nv_bfloat16* L, int off, float4 v) {
    __nv_bfloat16 h0 = __float2bfloat16(v.x), h1 = __float2bfloat16(v.y);
    __nv_bfloat16 h2 = __float2bfloat16(v.z), h3 = __float2bfloat16(v.w);
    *(__nv_bfloat162*)(H + off)     = __nv_bfloat162(h0, h1);
    *(__nv_bfloat162*)(H + off + 2) = __nv_bfloat162(h2, h3);
    *(__nv_bfloat162*)(L + off) = __nv_bfloat162(
        __float2bfloat16(v.x - __bfloat162float(h0)),
        __float2bfloat16(v.y - __bfloat162float(h1)));
    *(__nv_bfloat162*)(L + off + 2) = __nv_bfloat162(
        __float2bfloat16(v.z - __bfloat162float(h2)),
        __float2bfloat16(v.w - __bfloat162float(h3)));
}

// ====== heads: dual GEMM (mu, lv). MODE 0: main pass. MODE 1: protected-row cleanup. ======
template<int MODE>
__global__ void __launch_bounds__(256, 2) heads_wmma(
    const float* __restrict__ enc2f,
    const __nv_bfloat16* __restrict__ e2h, const __nv_bfloat16* __restrict__ e2l,
    const float* __restrict__ W3f, const float* __restrict__ W4f,
    const __nv_bfloat16* __restrict__ W3h, const __nv_bfloat16* __restrict__ W3l,
    const __nv_bfloat16* __restrict__ W4h, const __nv_bfloat16* __restrict__ W4l,
    const float* __restrict__ b3, const float* __restrict__ b4,
    const float* __restrict__ eps,
    float* __restrict__ dstZ, __nv_bfloat16* __restrict__ zhi,
    float* __restrict__ klpart) {
    extern __shared__ __align__(16) char sm[];
    __nv_bfloat16* Ah  = (__nv_bfloat16*)sm;
    __nv_bfloat16* Al  = Ah + 128 * HLDA;
    __nv_bfloat16* P3h = Al + 128 * HLDA;
    __nv_bfloat16* P3l = P3h + 64 * LDW;
    __nv_bfloat16* P4h = P3l + 64 * LDW;
    __nv_bfloat16* P4l = P4h + 64 * LDW;
    int tid = threadIdx.x, wid = tid >> 5;
    int wm0 = (wid >> 1) * 32, wn0 = (wid & 1) * 32;
    int rowBase;
    if (MODE == 0) rowBase = blockIdx.y * 128;
    else           rowBase = (blockIdx.y < 2) ? 256 + blockIdx.y * 128
                                              : 3584 + (blockIdx.y - 2) * 128;
    int colBase = blockIdx.x * 64;

    wmma::fragment<wmma::accumulator, 16, 16, 16, float> ac3[2][2], ac4[2][2];
#pragma unroll
    for (int m = 0; m < 2; m++)
#pragma unroll
        for (int n = 0; n < 2; n++) {
            wmma::fill_fragment(ac3[m][n], 0.f);
            wmma::fill_fragment(ac4[m][n], 0.f);
        }

    for (int kc = 0; kc < 4; kc++) {
        int kg = kc * 64;
        if (MODE == 0) {
            for (int idx = tid; idx < 128 * 8; idx += 256) {
                int r = idx >> 3, c8 = (idx & 7) << 3;
                size_t g = (size_t)(rowBase + r) * 256 + kg + c8;
                *(uint4*)&Ah[r * HLDA + c8] = *(const uint4*)(e2h + g);
                *(uint4*)&Al[r * HLDA + c8] = *(const uint4*)(e2l + g);
            }
            for (int idx = tid; idx < 64 * 8; idx += 256) {
                int k = idx >> 3, c8 = (idx & 7) << 3;
                size_t g = (size_t)(kg + k) * 256 + colBase + c8;
                *(uint4*)&P3h[k * LDW + c8] = *(const uint4*)(W3h + g);
                *(uint4*)&P3l[k * LDW + c8] = *(const uint4*)(W3l + g);
                *(uint4*)&P4h[k * LDW + c8] = *(const uint4*)(W4h + g);
                *(uint4*)&P4l[k * LDW + c8] = *(const uint4*)(W4l + g);
            }
        } else {
            for (int idx = tid; idx < 128 * 16; idx += 256) {
                int r = idx >> 4, c4 = (idx & 15) << 2;
                float4 v = *(const float4*)(enc2f + (size_t)(rowBase + r) * 256 + kg + c4);
                split4s(Ah, Al, r * HLDA + c4, v);
            }
            for (int idx = tid; idx < 64 * 16; idx += 256) {
                int k = idx >> 4, c4 = (idx & 15) << 2;
                size_t g = (size_t)(kg + k) * 256 + colBase + c4;
                split4s(P3h, P3l, k * LDW + c4, *(const float4*)(W3f + g));
                split4s(P4h, P4l, k * LDW + c4, *(const float4*)(W4f + g));
            }
        }
        __syncthreads();
#pragma unroll
        for (int ks = 0; ks < 4; ks++) {
            int k0 = ks * 16;
            wmma::fragment<wmma::matrix_a, 16, 16, 16, __nv_bfloat16, wmma::row_major> aH[2], aL[2];
#pragma unroll
            for (int m = 0; m < 2; m++) {
                wmma::load_matrix_sync(aH[m], &Ah[(wm0 + m * 16) * HLDA + k0], HLDA);
                wmma::load_matrix_sync(aL[m], &Al[(wm0 + m * 16) * HLDA + k0], HLDA);
            }
            {
                wmma::fragment<wmma::matrix_b, 16, 16, 16, __nv_bfloat16, wmma::row_major> bH[2], bL[2];
#pragma unroll
                for (int n = 0; n < 2; n++) {
                    wmma::load_matrix_sync(bH[n], &P3h[k0 * LDW + wn0 + n * 16], LDW);
                    wmma::load_matrix_sync(bL[n], &P3l[k0 * LDW + wn0 + n * 16], LDW);
                }
#pragma unroll
                for (int m = 0; m < 2; m++)
#pragma unroll
                    for (int n = 0; n < 2; n++) {
                        wmma::mma_sync(ac3[m][n], aH[m], bH[n], ac3[m][n]);
                        wmma::mma_sync(ac3[m][n], aL[m], bH[n], ac3[m][n]);
                        wmma::mma_sync(ac3[m][n], aH[m], bL[n], ac3[m][n]);
                    }
            }
            {
                wmma::fragment<wmma::matrix_b, 16, 16, 16, __nv_bfloat16, wmma::row_major> bH[2], bL[2];
#pragma unroll
                for (int n = 0; n < 2; n++) {
                    wmma::load_matrix_sync(bH[n], &P4h[k0 * LDW + wn0 + n * 16], LDW);
                    wmma::load_matrix_sync(bL[n], &P4l[k0 * LDW + wn0 + n * 16], LDW);
                }
#pragma unroll
                for (int m = 0; m < 2; m++)
#pragma unroll
                    for (int n = 0; n < 2; n++) {
                        wmma::mma_sync(ac4[m][n], aH[m], bH[n], ac4[m][n]);
                        wmma::mma_sync(ac4[m][n], aL[m], bH[n], ac4[m][n]);
                        wmma::mma_sync(ac4[m][n], aH[m], bL[n], ac4[m][n]);
                    }
            }
        }
        __syncthreads();
    }

    float* Cmu = (float*)sm;
    float* Clv = Cmu + 128 * LDC;
#pragma unroll
    for (int m = 0; m < 2; m++)
#pragma unroll
        for (int n = 0; n < 2; n++) {
            wmma::store_matrix_sync(&Cmu[(wm0 + m * 16) * LDC + wn0 + n * 16],
                                    ac3[m][n], LDC, wmma::mem_row_major);
            wmma::store_matrix_sync(&Clv[(wm0 + m * 16) * LDC + wn0 + n * 16],
                                    ac4[m][n], LDC, wmma::mem_row_major);
        }
    __syncthreads();

    bool zwrite = (MODE == 1) || !row_protected(rowBase);
    float klsum = 0.f;
#pragma unroll
    for (int rb = 0; rb < 8; rb++) {
        int r = rb * 16 + (tid >> 4);
        int c = (tid & 15) << 2;
        int n = rowBase + r;
        int col = colBase + c;
        float4 mu4 = *(float4*)&Cmu[r * LDC + c];
        float4 lv4 = *(float4*)&Clv[r * LDC + c];
        float4 b3v = *(const float4*)(b3 + col);
        float4 b4v = *(const float4*)(b4 + col);
        float mu[4] = {mu4.x + b3v.x, mu4.y + b3v.y, mu4.z + b3v.z, mu4.w + b3v.w};
        float lv[4] = {lv4.x + b4v.x, lv4.y + b4v.y, lv4.z + b4v.z, lv4.w + b4v.w};
        float sg[4];
#pragma unroll
        for (int j = 0; j < 4; j++) sg[j] = __expf(0.5f * lv[j]);

        float4 es = make_float4(0.f, 0.f, 0.f, 0.f);
#pragma unroll
        for (int k = 0; k < KK; k++) {
            float4 e = *(const float4*)(eps + (size_t)(n * KK + k) * DD + col);
            if (MODE == 0) { es.x += e.x; es.y += e.y; es.z += e.z; es.w += e.w; }
            if (zwrite) {
                float4 o;
                o.x = fmaf(sg[0], e.x, mu[0]);
                o.y = fmaf(sg[1], e.y, mu[1]);
                o.z = fmaf(sg[2], e.z, mu[2]);
                o.w = fmaf(sg[3], e.w, mu[3]);
                *(float4*)(dstZ + (size_t)(n * KK + k) * DD + col) = o;
            }
        }
        if (MODE == 0) {
            float zv[4];
            zv[0] = fmaf(sg[0], es.x * 0.125f, mu[0]);
            zv[1] = fmaf(sg[1], es.y * 0.125f, mu[1]);
            zv[2] = fmaf(sg[2], es.z * 0.125f, mu[2]);
            zv[3] = fmaf(sg[3], es.w * 0.125f, mu[3]);
            size_t base = (size_t)n * DD + col;
            *(__nv_bfloat162*)(zhi + base) =
                __nv_bfloat162(__float2bfloat16(zv[0]), __float2bfloat16(zv[1]));
            *(__nv_bfloat162*)(zhi + base + 2) =
                __nv_bfloat162(__float2bfloat16(zv[2]), __float2bfloat16(zv[3]));
#pragma unroll
            for (int j = 0; j < 4; j++)
                klsum += 1.f + lv[j] - mu[j] * mu[j] - sg[j] * sg[j];
        }
    }

    if (MODE == 0) {
        __shared__ float sred[256];
        sred[tid] = klsum; __syncthreads();
        for (int s = 128; s > 0; s >>= 1) {
            if (tid < s) sred[tid] += sred[tid + s];
            __syncthreads();
        }
        if (tid == 0) klpart[blockIdx.y * 4 + blockIdx.x] = sred[0];
    }
}

// ====== WMMA bf16 loss: Zl@Zl^T + BCE, 128x128 tiles, vectorized epilogue ======
__global__ void __launch_bounds__(256, 2) loss_mma_kernel(
    const __nv_bfloat16* __restrict__ zhi,
    const float* __restrict__ ADJ, float* __restrict__ glpart) {
    int bi = blockIdx.y, bj = blockIdx.x;
    int tid = threadIdx.x;
    if (bj < bi) {
        if (tid == 0) glpart[bi * 64 + bj] = 0.f;
        return;
    }
    int rowBase = bi * 128, colBase = bj * 128;

    extern __shared__ __align__(16) char smc[];
    __nv_bfloat16* AH = (__nv_bfloat16*)smc;
    __nv_bfloat16* BH = AH + 128 * LDA;

    int wid = tid >> 5;
    int wm0 = (wid >> 1) * 32;
    int wn0 = (wid & 1) * 64;

    wmma::fragment<wmma::accumulator, 16, 16, 16, float> acc[2][4];
#pragma unroll
    for (int m = 0; m < 2; m++)
#pragma unroll
        for (int n = 0; n < 4; n++) wmma::fill_fragment(acc[m][n], 0.f);

    for (int kc = 0; kc < 2; kc++) {
        int kg = kc * 128;
        for (int idx = tid; idx < 128 * 16; idx += 256) {
            int r = idx >> 4, c8 = (idx & 15) << 3;
            *(uint4*)&AH[r * LDA + c8] =
                *(const uint4*)(zhi + (size_t)(rowBase + r) * 256 + kg + c8);
            *(uint4*)&BH[r * LDA + c8] =
                *(const uint4*)(zhi + (size_t)(colBase + r) * 256 + kg + c8);
        }
        __syncthreads();
#pragma unroll
        for (int ks = 0; ks < 8; ks++) {
            int k0 = ks * 16;
            wmma::fragment<wmma::matrix_a, 16, 16, 16, __nv_bfloat16, wmma::row_major> aH[2];
#pragma unroll
            for (int m = 0; m < 2; m++)
                wmma::load_matrix_sync(aH[m], &AH[(wm0 + m * 16) * LDA + k0], LDA);
#pragma unroll
            for (int n = 0; n < 4; n++) {
                wmma::fragment<wmma::matrix_b, 16, 16, 16, __nv_bfloat16, wmma::col_major> bH;
                wmma::load_matrix_sync(bH, &BH[(wn0 + n * 16) * LDA + k0], LDA);
#pragma unroll
                for (int m = 0; m < 2; m++)
                    wmma::mma_sync(acc[m][n], aH[m], bH, acc[m][n]);
            }
        }
        __syncthreads();
    }

    float* Cs = (float*)smc;
#pragma unroll
    for (int m = 0; m < 2; m++)
#pragma unroll
        for (int n = 0; n < 4; n++)
            wmma::store_matrix_sync(&Cs[(wm0 + m * 16) * LDC2 + wn0 + n * 16],
                                    acc[m][n], LDC2, wmma::mem_row_major);
    __syncthreads();

    float term = 0.f;
    bool offdiag = (bi != bj);
    // loop1: softplus + ADJ[i][j], lanes cover 4 consecutive j
    {
        int jl4 = (tid & 31) << 2;
        int j0 = colBase + jl4;
        for (int il = tid >> 5; il < 128; il += 8) {
            int i = rowBase + il;
            float4 c4 = *(float4*)&Cs[il * LDC2 + jl4];
            float4 a4 = *(const float4*)(ADJ + (size_t)i * NN + j0);
            float cs[4] = {c4.x, c4.y, c4.z, c4.w};
            float as[4] = {a4.x, a4.y, a4.z, a4.w};
            if (offdiag || i < j0) {          // whole vec strictly upper
#pragma unroll
                for (int t = 0; t < 4; t++) {
                    float c = cs[t];
                    float sp = fmaxf(c, 0.f) + __logf(1.f + __expf(-fabsf(c)));
                    term += 2.f * sp - c * as[t];
                }
            } else {
#pragma unroll
                for (int t = 0; t < 4; t++) {
                    int j = j0 + t;
                    if (i > j) continue;
                    float c = cs[t];
                    float sp = fmaxf(c, 0.f) + __logf(1.f + __expf(-fabsf(c)));
                    term += (i < j ? 2.f : 1.f) * sp - c * as[t];
                }
            }
        }
    }
    // loop2: -c * ADJ[j][i], lanes cover 4 consecutive i
    {
        int il4 = (tid & 31) << 2;
        int i0 = rowBase + il4;
        for (int jl = tid >> 5; jl < 128; jl += 8) {
            int j = colBase + jl;
            float4 a4 = *(const float4*)(ADJ + (size_t)j * NN + i0);
            float as[4] = {a4.x, a4.y, a4.z, a4.w};
            if (offdiag || i0 + 3 < j) {
#pragma unroll
                for (int t = 0; t < 4; t++)
                    term -= Cs[(il4 + t) * LDC2 + jl] * as[t];
            } else {
#pragma unroll
                for (int t = 0; t < 4; t++)
                    if (i0 + t < j)
                        term -= Cs[(il4 + t) * LDC2 + jl] * as[t];
            }
        }
    }

    __shared__ float sred[256];
    sred[tid] = term; __syncthreads();
    for (int s = 128; s > 0; s >>= 1) {
        if (tid < s) sred[tid] += sred[tid + s];
        __syncthreads();
    }
    if (tid == 0) glpart[bi * 64 + bj] = sred[0];
}

// ================= final reduction =================
__global__ void finalize_kernel(const float* __restrict__ klpart,
                                const float* __restrict__ glpart,
                                float* __restrict__ outScalar) {
    __shared__ double sk[256], sg[256];
    int t = threadIdx.x;
    double a = (double)klpart[t];
    double b = 0.0;
    for (int i = t; i < 4096; i += 256) b += (double)glpart[i];
    sk[t] = a; sg[t] = b; __syncthreads();
    for (int s = 128; s > 0; s >>= 1) {
        if (t < s) { sk[t] += sk[t + s]; sg[t] += sg[t + s]; }
        __syncthreads();
    }
    if (t == 0) {
        double kl = -0.5 * sk[0] / (double)NN;
        double gl = sg[0] / ((double)NN * (double)NN);
        *outScalar = (float)(kl + gl);
    }
}

// ================= host launcher =================
extern "C" void kernel_launch(void* const* d_in, const int* in_sizes, int n_in,
                              void* d_out, int out_size) {
    const float* enc = (const float*)d_in[0];
    const int*   ei  = (const int*)d_in[1];
    const float* w   = (const float*)d_in[2];
    const float* ADJ = (const float*)d_in[3];
    const float* eps = (const float*)d_in[4];
    const float* W1 = (const float*)d_in[5];  const float* b1 = (const float*)d_in[6];
    const float* W2 = (const float*)d_in[7];  const float* b2 = (const float*)d_in[8];
    const float* W3 = (const float*)d_in[9];  const float* b3 = (const float*)d_in[10];
    const float* W4 = (const float*)d_in[11]; const float* b4 = (const float*)d_in[12];

    float* out  = (float*)d_out;
    float* enc2 = out;
    float* zreg = out + (size_t)NN * DD;

    int*   deg  = (int*)  (zreg + S_DEG);
    int*   off  = (int*)  (zreg + S_OFF);
    int*   cur  = (int*)  (zreg + S_CUR);
    int*   esrc = (int*)  (zreg + S_ESRC);
    float* ew   =          zreg + S_EW;
    __nv_bfloat16* wsp = (__nv_bfloat16*)(zreg + S_WSP);
    __nv_bfloat16* hch = (__nv_bfloat16*)(zreg + S_HCH);
    __nv_bfloat16* hcl = (__nv_bfloat16*)(zreg + S_HCL);
    float* h1   =          zreg + S_H1;
    __nv_bfloat16* e2h = (__nv_bfloat16*)(zreg + S_E2H);
    __nv_bfloat16* e2l = (__nv_bfloat16*)(zreg + S_E2L);
    __nv_bfloat16* zhi = (__nv_bfloat16*)(zreg + S_ZLH);
    float* klp  =          zreg + S_KLP;
    float* glp  =          zreg + S_GLP;
    float* outScalar = out + (size_t)out_size - 1;

    cudaFuncSetAttribute(loss_mma_kernel,
                         cudaFuncAttributeMaxDynamicSharedMemorySize, LOSS_SMEM);
    cudaFuncSetAttribute(gemm_bf16<true, false, false, 512>,
                         cudaFuncAttributeMaxDynamicSharedMemorySize, GW_SMEM);
    cudaFuncSetAttribute(gemm_bf16<true, true, true, 512>,
                         cudaFuncAttributeMaxDynamicSharedMemorySize, GW_SMEM);
    cudaFuncSetAttribute(heads_wmma<0>,
                         cudaFuncAttributeMaxDynamicSharedMemorySize, HD_SMEM);
    cudaFuncSetAttribute(heads_wmma<1>,
                         cudaFuncAttributeMaxDynamicSharedMemorySize, HD_SMEM);

    // weight pre-split + deg zero (fused), then CSR build
    split_w_all<<<384, 256>>>(W1, W2, W3, W4, wsp, deg);
    hist_kernel<<<EE / 256, 256>>>(ei, deg);
    scan_kernel<<<1, 256>>>(deg, off, cur);
    fill_kernel<<<EE / 256, 256>>>(ei, w, cur, esrc, ew);

    // conv1 + linear1 + relu
    gather_kernel<<<NN, 256>>>(enc, hch, hcl, deg, off, esrc, ew);
    gemm_bf16<true, false, false, 512><<<dim3(2, 64), 256, GW_SMEM>>>(
        hch, hcl, wsp + W1H, wsp + W1L, b1, nullptr, h1, nullptr, nullptr);

    // conv2 + linear2 + relu + residual -> enc2 (+ split copies)
    gather_kernel<<<NN, 256>>>(h1, hch, hcl, deg, off, esrc, ew);
    gemm_bf16<true, true, true, 512><<<dim3(2, 64), 256, GW_SMEM>>>(
        hch, hcl, wsp + W2H, wsp + W2L, b2, enc, enc2, e2h, e2l);

    // heads: dual GEMM -> Zl + KL partials + Z for non-protected rows
    heads_wmma<0><<<dim3(4, 64), 256, HD_SMEM>>>(
        nullptr, e2h, e2l, nullptr, nullptr,
        wsp + W3H, wsp + W3L, wsp + W4H, wsp + W4L,
        b3, b4, eps, zreg, zhi, klp);

    // loss GEMM + BCE
    loss_mma_kernel<<<dim3(64, 64), 256, LOSS_SMEM>>>(zhi, ADJ, glp);

    // loss scalar (reads klp/glp before cleanup overwrites them)
    finalize_kernel<<<1, 256>>>(klp, glp, outScalar);

    // cleanup: write Z for the 15 protected row-blocks (self-splitting)
    heads_wmma<1><<<dim3(4, 15), 256, HD_SMEM>>>(
        enc2, nullptr, nullptr, W3, W4,
        nullptr, nullptr, nullptr, nullptr,
        b3, b4, eps, zreg, nullptr, nullptr);
}